// round 13
// baseline (speedup 1.0000x reference)
#include <cuda_runtime.h>
#include <cuda_fp16.h>
#include <cstdint>
#include <math.h>

#define B_ 4
#define S_ 2048
#define E_ 1024
#define H_ 16
#define D_ 64
#define M_ (B_*S_)   // 8192

// ---- scratch (static device allocations; runtime alloc is forbidden) ----
__device__ __half g_xh[(size_t)M_*E_];
__device__ __half g_Wq[(size_t)E_*E_];
__device__ __half g_Wk[(size_t)E_*E_];
__device__ __half g_Wo[(size_t)E_*E_];
__device__ __half g_Qh[(size_t)M_*E_];   // Q projection (fp16); also serves as V
__device__ __half g_Kh[(size_t)M_*E_];   // K projection (fp16)
__device__ __half g_Ah[(size_t)M_*E_];   // attention output (fp16)

// ============================ helpers ============================
__device__ __forceinline__ void cp16s(uint32_t dst, const void* src) {
    asm volatile("cp.async.cg.shared.global [%0], [%1], 16;" :: "r"(dst), "l"(src));
}
__device__ __forceinline__ void cp_commit() { asm volatile("cp.async.commit_group;"); }
__device__ __forceinline__ void cp_wait0()  { asm volatile("cp.async.wait_group 0;"); }
__device__ __forceinline__ void cp_wait1()  { asm volatile("cp.async.wait_group 1;"); }

__device__ __forceinline__ void mbar_init(uint32_t a, uint32_t n) {
    asm volatile("mbarrier.init.shared.b64 [%0], %1;" :: "r"(a), "r"(n) : "memory");
}
__device__ __forceinline__ void mbar_arrive(uint32_t a) {
    asm volatile("mbarrier.arrive.shared.b64 _, [%0];" :: "r"(a) : "memory");
}
__device__ __forceinline__ void cp_async_mbar_arrive_noinc(uint32_t a) {
    asm volatile("cp.async.mbarrier.arrive.noinc.shared::cta.b64 [%0];" :: "r"(a) : "memory");
}
__device__ __forceinline__ void mbar_wait(uint32_t a, uint32_t parity) {
    asm volatile(
        "{\n\t.reg .pred P;\n\t"
        "WAITLP_%=:\n\t"
        "mbarrier.try_wait.parity.acquire.cta.shared::cta.b64 P, [%0], %1, 0x989680;\n\t"
        "@P bra.uni WAITDN_%=;\n\t"
        "bra.uni WAITLP_%=;\n\t"
        "WAITDN_%=:\n\t}"
        :: "r"(a), "r"(parity) : "memory");
}

__device__ __forceinline__ void ldsm4(uint32_t& r0, uint32_t& r1, uint32_t& r2, uint32_t& r3,
                                      uint32_t addr) {
    asm volatile("ldmatrix.sync.aligned.m8n8.x4.shared.b16 {%0,%1,%2,%3}, [%4];"
                 : "=r"(r0), "=r"(r1), "=r"(r2), "=r"(r3) : "r"(addr));
}
__device__ __forceinline__ void ldsm4t(uint32_t& r0, uint32_t& r1, uint32_t& r2, uint32_t& r3,
                                       uint32_t addr) {
    asm volatile("ldmatrix.sync.aligned.m8n8.x4.trans.shared.b16 {%0,%1,%2,%3}, [%4];"
                 : "=r"(r0), "=r"(r1), "=r"(r2), "=r"(r3) : "r"(addr));
}
// mma m16n8k16 fp16 in, fp32 accum (baseline ISA)
__device__ __forceinline__ void mma16816(float* c, uint32_t a0, uint32_t a1, uint32_t a2,
                                         uint32_t a3, uint32_t b0, uint32_t b1) {
    asm volatile(
        "mma.sync.aligned.m16n8k16.row.col.f32.f16.f16.f32 "
        "{%0,%1,%2,%3},{%4,%5,%6,%7},{%8,%9},{%0,%1,%2,%3};"
        : "+f"(c[0]), "+f"(c[1]), "+f"(c[2]), "+f"(c[3])
        : "r"(a0), "r"(a1), "r"(a2), "r"(a3), "r"(b0), "r"(b1));
}
__device__ __forceinline__ uint32_t h2u(__half2 h) { return *(uint32_t*)&h; }
__device__ __forceinline__ uint32_t h2exp2(uint32_t x) {
    uint32_t r;
    asm volatile("ex2.approx.f16x2 %0, %1;" : "=r"(r) : "r"(x));
    return r;
}

// ============================================================================
// fp32 -> fp16 convert, ALL tensors in one launch
// ============================================================================
__global__ void f2h_all_kernel(const float* __restrict__ x,  const float* __restrict__ Wq,
                               const float* __restrict__ Wk, const float* __restrict__ Wo,
                               __half* __restrict__ xh, __half* __restrict__ wq,
                               __half* __restrict__ wk, __half* __restrict__ wo)
{
    const int NX = (M_ * E_) / 4;
    const int NW = (E_ * E_) / 4;
    int i = blockIdx.x * blockDim.x + threadIdx.x;
    const float* in;
    __half* out;
    int off;
    if (i < NX) { in = x; out = xh; off = i; }
    else {
        int j = i - NX;
        int seg = j / NW, r = j - seg * NW;
        in  = (seg == 0) ? Wq : (seg == 1) ? Wk : Wo;
        out = (seg == 0) ? wq : (seg == 1) ? wk : wo;
        off = r;
    }
    float4 v = ((const float4*)in)[off];
    ((__half2*)out)[2*off]     = __floats2half2_rn(v.x, v.y);
    ((__half2*)out)[2*off + 1] = __floats2half2_rn(v.z, v.w);
}

// ============================================================================
// fp16 tensor-core NT GEMM — EXACT R11 config (measured best: 53us O-proj).
// CTA 128x128, BK=64, 256 thr, warps 2(M)x4(N), warp tile 64x32.
// 3-stage cp.async pipeline, one sync per k-tile. DUAL=1: bx&1 selects W/C.
// ============================================================================
#define GT_BYTES 16384
#define STG_BYTES (2 * GT_BYTES)
#define GEMM_SMEM (3 * STG_BYTES)

template<int BIAS, int DUAL>
__global__ void __launch_bounds__(256, 2)
gemm_h_kernel(const __half* __restrict__ A, const __half* __restrict__ W,
              const float* __restrict__ bias, void* __restrict__ Cout,
              const __half* __restrict__ W2, void* __restrict__ Cout2,
              int M, int N, int K)
{
    extern __shared__ __half smh[];
    const uint32_t uS = (uint32_t)__cvta_generic_to_shared(smh);

    const int tid = threadIdx.x;
    const int wid = tid >> 5, lane = tid & 31;
    const int g = lane >> 2, tig = lane & 3;
    const int wm = wid & 1, wn = wid >> 1;
    const int row0 = blockIdx.y * 128;
    int col0;
    const __half* Wm;
    void* Cm;
    if (DUAL) {
        col0 = ((int)blockIdx.x >> 1) * 128;
        if (blockIdx.x & 1) { Wm = W2; Cm = Cout2; }
        else                { Wm = W;  Cm = Cout;  }
    } else {
        col0 = blockIdx.x * 128;
        Wm = W; Cm = Cout;
    }

    float acc[4][4][4];
    #pragma unroll
    for (int mi = 0; mi < 4; mi++)
        #pragma unroll
        for (int ni = 0; ni < 4; ni++)
            #pragma unroll
            for (int r = 0; r < 4; r++) acc[mi][ni][r] = 0.f;

    auto tload = [&](int kt, int st) {
        const uint32_t base = uS + st * STG_BYTES;
        #pragma unroll
        for (int j = 0; j < 4; j++) {
            const int idx = tid + 256 * j;
            const int r = idx >> 3, c = idx & 7;
            const uint32_t off = (r * 64 + ((c ^ (r & 7)) << 3)) * 2;
            cp16s(base + off,            A  + (size_t)(row0 + r) * K + kt * 64 + c * 8);
            cp16s(base + GT_BYTES + off, Wm + (size_t)(col0 + r) * K + kt * 64 + c * 8);
        }
    };

    tload(0, 0); cp_commit();
    tload(1, 1); cp_commit();

    const int NT = K >> 6;
    int st = 0;
    for (int kt = 0; kt < NT; kt++) {
        if (kt + 1 < NT) cp_wait1(); else cp_wait0();
        __syncthreads();
        if (kt + 2 < NT) {
            int sp = st + 2; if (sp >= 3) sp -= 3;
            tload(kt + 2, sp); cp_commit();
        }

        const uint32_t bA = uS + st * STG_BYTES;
        const uint32_t bB = bA + GT_BYTES;
        #pragma unroll
        for (int ks = 0; ks < 4; ks++) {
            uint32_t bb[4][2];
            #pragma unroll
            for (int p = 0; p < 2; p++) {
                const int rowb = wn * 32 + p * 16 + (lane & 7) + ((lane >= 16) ? 8 : 0);
                const int ch   = 2 * ks + ((lane >> 3) & 1);
                const uint32_t ad = bB + (rowb * 64 + ((ch ^ (rowb & 7)) << 3)) * 2;
                ldsm4(bb[2*p][0], bb[2*p][1], bb[2*p+1][0], bb[2*p+1][1], ad);
            }
            #pragma unroll
            for (int mi = 0; mi < 4; mi++) {
                const int rowa = wm * 64 + mi * 16 + (lane & 7) + (((lane >> 3) & 1) ? 8 : 0);
                const int ch   = 2 * ks + ((lane >> 4) & 1);
                const uint32_t ad = bA + (rowa * 64 + ((ch ^ (rowa & 7)) << 3)) * 2;
                uint32_t a0, a1, a2, a3;
                ldsm4(a0, a1, a2, a3, ad);
                #pragma unroll
                for (int ni = 0; ni < 4; ni++)
                    mma16816(acc[mi][ni], a0, a1, a2, a3, bb[ni][0], bb[ni][1]);
            }
        }
        if (++st == 3) st = 0;
    }

    #pragma unroll
    for (int mi = 0; mi < 4; mi++) {
        const int r = row0 + wm * 64 + mi * 16 + g;
        #pragma unroll
        for (int ni = 0; ni < 4; ni++) {
            const int c = col0 + wn * 32 + ni * 8 + 2 * tig;
            if (BIAS) {
                float* C = (float*)Cm;
                const float b0 = bias[c], b1 = bias[c + 1];
                *(float2*)(C + (size_t)r * N + c)       = make_float2(acc[mi][ni][0] + b0, acc[mi][ni][1] + b1);
                *(float2*)(C + (size_t)(r + 8) * N + c) = make_float2(acc[mi][ni][2] + b0, acc[mi][ni][3] + b1);
            } else {
                __half* C = (__half*)Cm;
                *(__half2*)(C + (size_t)r * N + c)       = __floats2half2_rn(acc[mi][ni][0], acc[mi][ni][1]);
                *(__half2*)(C + (size_t)(r + 8) * N + c) = __floats2half2_rn(acc[mi][ni][2], acc[mi][ni][3]);
            }
        }
    }
}

// ============================================================================
// fp16 tensor-core causal flash attention, V = Q (faithful to reference bug).
// CTA = (b, h, 128 q-rows), 4 warps x 32 q-rows, mbarrier pipeline (4 stages).
// SOFTWARE-PIPELINED: PV runs one tile behind QK; per-ks chunks of PV(kt-1)
// and softmax(kt) are hand-interleaved in one straight-line region so EX2/cvt
// fill the HMMA shadow (tensor pipe was idling during phase-separated softmax).
// Single ph buffer is WAR-safe: PV chunk reads ph before softmax chunk writes.
// Fully-masked warp-tiles (last diagonal tile, warps 0/1) skip all compute.
// ============================================================================
#define AT_STG 4
#define AT_TILE 16384                 // K 8KB + V 8KB per stage
#define ATTN_SMEM (AT_STG * AT_TILE)  // 64KB dynamic

__global__ void __launch_bounds__(128, 2)
attn_h_kernel(const __half* __restrict__ Qh, const __half* __restrict__ Kh,
              __half* __restrict__ Oh)
{
    extern __shared__ __half dynsm[];
    __shared__ uint64_t mbars[8];     // full[0..3], empty[4..7]

    const uint32_t uS = (uint32_t)__cvta_generic_to_shared(dynsm);
    const uint32_t uMF = (uint32_t)__cvta_generic_to_shared(&mbars[0]);
    const uint32_t uME = uMF + 32;

    const int qt = 15 - (int)blockIdx.x;          // heavy blocks first
    const int h  = blockIdx.y;
    const int b  = blockIdx.z;
    const int tid = threadIdx.x;
    const int wid = tid >> 5, lane = tid & 31;
    const int g = lane >> 2, tig = lane & 3;
    const int rbase = qt * 128 + wid * 32 + g;
    const int rmaxw = qt * 128 + wid * 32 + 31;   // max q-row this warp owns

    if (tid == 0) {
        #pragma unroll
        for (int s = 0; s < 4; s++) {
            mbar_init(uMF + 8 * s, 32);    // producer warp's 32 threads
            mbar_init(uME + 8 * s, 128);   // all 128 threads arrive per round
        }
    }
    __syncthreads();   // only barrier in the kernel

    size_t gr[2][2];
    #pragma unroll
    for (int mb = 0; mb < 2; mb++) {
        gr[mb][0] = (size_t)(b * S_ + rbase + mb * 16) * E_ + h * 64;
        gr[mb][1] = gr[mb][0] + (size_t)8 * E_;
    }

    // Q a-fragments (held in registers for whole kernel)
    uint32_t qa[2][4][4];
    #pragma unroll
    for (int mb = 0; mb < 2; mb++)
        #pragma unroll
        for (int ks = 0; ks < 4; ks++) {
            const int c0 = 16 * ks + 2 * tig;
            qa[mb][ks][0] = *(const uint32_t*)(Qh + gr[mb][0] + c0);
            qa[mb][ks][1] = *(const uint32_t*)(Qh + gr[mb][1] + c0);
            qa[mb][ks][2] = *(const uint32_t*)(Qh + gr[mb][0] + c0 + 8);
            qa[mb][ks][3] = *(const uint32_t*)(Qh + gr[mb][1] + c0 + 8);
        }

    float of[2][8][4];
    #pragma unroll
    for (int mb = 0; mb < 2; mb++)
        #pragma unroll
        for (int nj = 0; nj < 8; nj++)
            #pragma unroll
            for (int r = 0; r < 4; r++) of[mb][nj][r] = 0.f;
    float lsum[2][2] = {{0.f, 0.f}, {0.f, 0.f}};

    uint32_t ph[2][2][8];            // probabilities of the PREVIOUS tile
    float sf[2][8][4];               // current tile scores
    const float FS = 0.03125f * 1.44269504f;   // (1/sqrt(E)) * log2(e)

    const int nkt = 2 * qt + 2;

    // producer: fill stage (kt&3) with K/V tile kt (warp-wide)
    auto produce = [&](int kt) {
        const int s = kt & 3;
        const int r = kt >> 2;
        if (r > 0) mbar_wait(uME + 8 * s, (uint32_t)((r - 1) & 1));
        const uint32_t base = uS + s * AT_TILE;
        #pragma unroll
        for (int j = 0; j < 16; j++) {
            const int idx = lane + 32 * j;
            const int rr = idx >> 3, cc = idx & 7;
            const uint32_t off = (rr * 64 + ((cc ^ (rr & 7)) << 3)) * 2;
            const size_t gsrc = (size_t)(b * S_ + kt * 64 + rr) * E_ + h * 64 + cc * 8;
            cp16s(base + off,        Kh + gsrc);
            cp16s(base + 8192 + off, Qh + gsrc);   // V = Q
        }
        cp_async_mbar_arrive_noinc(uMF + 8 * s);
    };

    // PV chunk: V rows 16ks..16ks+15 of previous tile, all 8 nj column-blocks
    auto pv_chunk = [&](int ks, uint32_t bVp) {
        uint32_t bb[8][2];
        #pragma unroll
        for (int p = 0; p < 4; p++) {
            const int rowb = 16 * ks + (lane & 7) + (((lane >> 3) & 1) ? 8 : 0);
            const int ch   = 2 * p + ((lane >= 16) ? 1 : 0);
            const uint32_t ad = bVp + (rowb * 64 + ((ch ^ (rowb & 7)) << 3)) * 2;
            ldsm4t(bb[2*p][0], bb[2*p][1], bb[2*p+1][0], bb[2*p+1][1], ad);
        }
        #pragma unroll
        for (int nj = 0; nj < 8; nj++) {
            mma16816(of[0][nj], ph[0][0][2*ks], ph[0][1][2*ks],
                     ph[0][0][2*ks+1], ph[0][1][2*ks+1], bb[nj][0], bb[nj][1]);
            mma16816(of[1][nj], ph[1][0][2*ks], ph[1][1][2*ks],
                     ph[1][0][2*ks+1], ph[1][1][2*ks+1], bb[nj][0], bb[nj][1]);
        }
    };

    __half2 ls0[2], ls1[2];
    // softmax chunk: converts sf pairs (2ks, 2ks+1) -> ph, accumulates ls
    auto sm_chunk = [&](int ks, bool maskT, int k0) {
        #pragma unroll
        for (int q = 2 * ks; q <= 2 * ks + 1; q++) {
            #pragma unroll
            for (int mb = 0; mb < 2; mb++) {
                float t0, t1, t2, t3;
                if (maskT) {
                    const int rq = rbase + mb * 16;
                    const int kc = k0 + q * 8 + 2 * tig;
                    t0 = (kc     <= rq)     ? sf[mb][q][0] * FS : -100.f;
                    t1 = (kc + 1 <= rq)     ? sf[mb][q][1] * FS : -100.f;
                    t2 = (kc     <= rq + 8) ? sf[mb][q][2] * FS : -100.f;
                    t3 = (kc + 1 <= rq + 8) ? sf[mb][q][3] * FS : -100.f;
                } else {
                    t0 = sf[mb][q][0] * FS; t1 = sf[mb][q][1] * FS;
                    t2 = sf[mb][q][2] * FS; t3 = sf[mb][q][3] * FS;
                }
                uint32_t px = h2exp2(h2u(__floats2half2_rn(t0, t1)));
                uint32_t py = h2exp2(h2u(__floats2half2_rn(t2, t3)));
                ph[mb][0][q] = px;
                ph[mb][1][q] = py;
                ls0[mb] = __hadd2(ls0[mb], *(__half2*)&px);
                ls1[mb] = __hadd2(ls1[mb], *(__half2*)&py);
            }
        }
    };

    bool prev_active = false;
    int s_prev = 0;

    // prologue: lookahead 2 (stage s_prev is held one extra iteration now)
    #pragma unroll
    for (int kp = 0; kp < 2; kp++)
        if (kp < nkt && (kp & 3) == wid) produce(kp);

    for (int kt = 0; kt < nkt; kt++) {
        {
            const int kp = kt + 2;
            if (kp < nkt && (kp & 3) == wid) produce(kp);
        }
        const int s = kt & 3;
        mbar_wait(uMF + 8 * s, (uint32_t)((kt >> 2) & 1));

        const uint32_t bK  = uS + s * AT_TILE;
        const uint32_t bVp = uS + s_prev * AT_TILE + 8192;
        const bool active = (kt * 64 <= rmaxw);
        const bool doPV   = (kt > 0) && prev_active;
        const bool maskT  = (kt >= 2 * qt);
        const int  k0     = kt * 64;

        // ---- S = Q K^T for both m-blocks ----
        if (active) {
            #pragma unroll
            for (int mb = 0; mb < 2; mb++)
                #pragma unroll
                for (int ni = 0; ni < 8; ni++)
                    #pragma unroll
                    for (int r = 0; r < 4; r++) sf[mb][ni][r] = 0.f;
            #pragma unroll
            for (int ks = 0; ks < 4; ks++) {
                uint32_t bb[8][2];
                #pragma unroll
                for (int p = 0; p < 4; p++) {
                    const int rowb = p * 16 + (lane & 7) + ((lane >= 16) ? 8 : 0);
                    const int ch   = 2 * ks + ((lane >> 3) & 1);
                    const uint32_t ad = bK + (rowb * 64 + ((ch ^ (rowb & 7)) << 3)) * 2;
                    ldsm4(bb[2*p][0], bb[2*p][1], bb[2*p+1][0], bb[2*p+1][1], ad);
                }
                #pragma unroll
                for (int ni = 0; ni < 8; ni++) {
                    mma16816(sf[0][ni], qa[0][ks][0], qa[0][ks][1], qa[0][ks][2], qa[0][ks][3],
                             bb[ni][0], bb[ni][1]);
                    mma16816(sf[1][ni], qa[1][ks][0], qa[1][ks][1], qa[1][ks][2], qa[1][ks][3],
                             bb[ni][0], bb[ni][1]);
                }
            }
        }

        ls0[0] = ls0[1] = ls1[0] = ls1[1] = __floats2half2_rn(0.f, 0.f);

        // ---- fused PV(kt-1) + softmax(kt), interleaved per ks chunk ----
        if (active && doPV) {
            if (maskT) {
                #pragma unroll
                for (int ks = 0; ks < 4; ks++) { pv_chunk(ks, bVp); sm_chunk(ks, true,  k0); }
            } else {
                #pragma unroll
                for (int ks = 0; ks < 4; ks++) { pv_chunk(ks, bVp); sm_chunk(ks, false, k0); }
            }
        } else if (active) {
            if (maskT) {
                #pragma unroll
                for (int ks = 0; ks < 4; ks++) sm_chunk(ks, true,  k0);
            } else {
                #pragma unroll
                for (int ks = 0; ks < 4; ks++) sm_chunk(ks, false, k0);
            }
        } else if (doPV) {
            #pragma unroll
            for (int ks = 0; ks < 4; ks++) pv_chunk(ks, bVp);
        }

        if (active) {
            #pragma unroll
            for (int mb = 0; mb < 2; mb++) {
                float2 f0 = __half22float2(ls0[mb]);
                float2 f1 = __half22float2(ls1[mb]);
                lsum[mb][0] += f0.x + f0.y;
                lsum[mb][1] += f1.x + f1.y;
            }
        }

        if (kt > 0) mbar_arrive(uME + 8 * s_prev);   // done with tile kt-1
        prev_active = active;
        s_prev = s;
    }

    // ---- epilogue: PV of the last tile ----
    if (prev_active) {
        const uint32_t bVp = uS + s_prev * AT_TILE + 8192;
        #pragma unroll
        for (int ks = 0; ks < 4; ks++) pv_chunk(ks, bVp);
    }
    mbar_arrive(uME + 8 * s_prev);

    // ---- quad-reduce l, normalize, store fp16 ----
    #pragma unroll
    for (int mb = 0; mb < 2; mb++) {
        float l0 = lsum[mb][0], l1 = lsum[mb][1];
        l0 += __shfl_xor_sync(0xffffffffu, l0, 1);
        l0 += __shfl_xor_sync(0xffffffffu, l0, 2);
        l1 += __shfl_xor_sync(0xffffffffu, l1, 1);
        l1 += __shfl_xor_sync(0xffffffffu, l1, 2);
        const float i0 = 1.f / l0, i1 = 1.f / l1;
        #pragma unroll
        for (int nj = 0; nj < 8; nj++) {
            const int c = nj * 8 + 2 * tig;
            *(__half2*)(Oh + gr[mb][0] + c) = __floats2half2_rn(of[mb][nj][0] * i0, of[mb][nj][1] * i0);
            *(__half2*)(Oh + gr[mb][1] + c) = __floats2half2_rn(of[mb][nj][2] * i1, of[mb][nj][3] * i1);
        }
    }
}

// ============================================================================
// launch
// ============================================================================
extern "C" void kernel_launch(void* const* d_in, const int* in_sizes, int n_in,
                              void* d_out, int out_size)
{
    (void)in_sizes; (void)n_in; (void)out_size;
    const float* x  = (const float*)d_in[0];
    const float* Wk = (const float*)d_in[1];
    const float* Wq = (const float*)d_in[2];
    // d_in[3] = Wv — computed-then-discarded in the reference; skipped.
    const float* Wo = (const float*)d_in[4];
    const float* bo = (const float*)d_in[5];
    float* out = (float*)d_out;

    __half *xh, *wq, *wk, *wo, *Qp, *Kp, *Ap;
    cudaGetSymbolAddress((void**)&xh, g_xh);
    cudaGetSymbolAddress((void**)&wq, g_Wq);
    cudaGetSymbolAddress((void**)&wk, g_Wk);
    cudaGetSymbolAddress((void**)&wo, g_Wo);
    cudaGetSymbolAddress((void**)&Qp, g_Qh);
    cudaGetSymbolAddress((void**)&Kp, g_Kh);
    cudaGetSymbolAddress((void**)&Ap, g_Ah);

    cudaFuncSetAttribute(gemm_h_kernel<0,1>, cudaFuncAttributeMaxDynamicSharedMemorySize, GEMM_SMEM);
    cudaFuncSetAttribute(gemm_h_kernel<1,0>, cudaFuncAttributeMaxDynamicSharedMemorySize, GEMM_SMEM);
    cudaFuncSetAttribute(attn_h_kernel,      cudaFuncAttributeMaxDynamicSharedMemorySize, ATTN_SMEM);

    const int NTOT = (M_ * E_ + 3 * E_ * E_) / 4;
    f2h_all_kernel<<<NTOT / 256, 256>>>(x, Wq, Wk, Wo, xh, wq, wk, wo);

    // fused Q+K projections: blockIdx.x&1 selects weight/output
    dim3 qkGrid(2 * E_ / 128, M_ / 128);   // (16, 64)
    gemm_h_kernel<0,1><<<qkGrid, 256, GEMM_SMEM>>>(xh, wq, nullptr, Qp, wk, Kp, M_, E_, E_);

    dim3 aGrid(S_ / 128, H_, B_);          // (16, 16, 4)
    attn_h_kernel<<<aGrid, 128, ATTN_SMEM>>>(Qp, Kp, Ap);

    dim3 oGrid(E_ / 128, M_ / 128);        // (8, 64)
    gemm_h_kernel<1,0><<<oGrid, 256, GEMM_SMEM>>>(Ap, wo, bo, out, nullptr, nullptr, M_, E_, E_);
}

// round 14
// speedup vs baseline: 1.1296x; 1.1296x over previous
#include <cuda_runtime.h>
#include <cuda_fp16.h>
#include <cstdint>
#include <math.h>

#define B_ 4
#define S_ 2048
#define E_ 1024
#define H_ 16
#define D_ 64
#define M_ (B_*S_)   // 8192

// ---- scratch (static device allocations; runtime alloc is forbidden) ----
__device__ __half g_xh[(size_t)M_*E_];
__device__ __half g_Wq[(size_t)E_*E_];
__device__ __half g_Wk[(size_t)E_*E_];
__device__ __half g_Wo[(size_t)E_*E_];
__device__ __half g_Qh[(size_t)M_*E_];   // Q projection (fp16); also serves as V
__device__ __half g_Kh[(size_t)M_*E_];   // K projection (fp16)
__device__ __half g_Ah[(size_t)M_*E_];   // attention output (fp16)

// ============================ helpers ============================
__device__ __forceinline__ void cp16s(uint32_t dst, const void* src) {
    asm volatile("cp.async.cg.shared.global [%0], [%1], 16;" :: "r"(dst), "l"(src));
}
__device__ __forceinline__ void cp_commit() { asm volatile("cp.async.commit_group;"); }
__device__ __forceinline__ void cp_wait0()  { asm volatile("cp.async.wait_group 0;"); }
__device__ __forceinline__ void cp_wait1()  { asm volatile("cp.async.wait_group 1;"); }

__device__ __forceinline__ void mbar_init(uint32_t a, uint32_t n) {
    asm volatile("mbarrier.init.shared.b64 [%0], %1;" :: "r"(a), "r"(n) : "memory");
}
__device__ __forceinline__ void mbar_arrive(uint32_t a) {
    asm volatile("mbarrier.arrive.shared.b64 _, [%0];" :: "r"(a) : "memory");
}
__device__ __forceinline__ void cp_async_mbar_arrive_noinc(uint32_t a) {
    asm volatile("cp.async.mbarrier.arrive.noinc.shared::cta.b64 [%0];" :: "r"(a) : "memory");
}
__device__ __forceinline__ void mbar_wait(uint32_t a, uint32_t parity) {
    asm volatile(
        "{\n\t.reg .pred P;\n\t"
        "WAITLP_%=:\n\t"
        "mbarrier.try_wait.parity.acquire.cta.shared::cta.b64 P, [%0], %1, 0x989680;\n\t"
        "@P bra.uni WAITDN_%=;\n\t"
        "bra.uni WAITLP_%=;\n\t"
        "WAITDN_%=:\n\t}"
        :: "r"(a), "r"(parity) : "memory");
}

__device__ __forceinline__ void ldsm4(uint32_t& r0, uint32_t& r1, uint32_t& r2, uint32_t& r3,
                                      uint32_t addr) {
    asm volatile("ldmatrix.sync.aligned.m8n8.x4.shared.b16 {%0,%1,%2,%3}, [%4];"
                 : "=r"(r0), "=r"(r1), "=r"(r2), "=r"(r3) : "r"(addr));
}
__device__ __forceinline__ void ldsm4t(uint32_t& r0, uint32_t& r1, uint32_t& r2, uint32_t& r3,
                                       uint32_t addr) {
    asm volatile("ldmatrix.sync.aligned.m8n8.x4.trans.shared.b16 {%0,%1,%2,%3}, [%4];"
                 : "=r"(r0), "=r"(r1), "=r"(r2), "=r"(r3) : "r"(addr));
}
// mma m16n8k16 fp16 in, fp32 accum (baseline ISA)
__device__ __forceinline__ void mma16816(float* c, uint32_t a0, uint32_t a1, uint32_t a2,
                                         uint32_t a3, uint32_t b0, uint32_t b1) {
    asm volatile(
        "mma.sync.aligned.m16n8k16.row.col.f32.f16.f16.f32 "
        "{%0,%1,%2,%3},{%4,%5,%6,%7},{%8,%9},{%0,%1,%2,%3};"
        : "+f"(c[0]), "+f"(c[1]), "+f"(c[2]), "+f"(c[3])
        : "r"(a0), "r"(a1), "r"(a2), "r"(a3), "r"(b0), "r"(b1));
}
__device__ __forceinline__ uint32_t h2u(__half2 h) { return *(uint32_t*)&h; }
__device__ __forceinline__ uint32_t h2exp2(uint32_t x) {
    uint32_t r;
    asm volatile("ex2.approx.f16x2 %0, %1;" : "=r"(r) : "r"(x));
    return r;
}

// ============================================================================
// fp32 -> fp16 convert, ALL tensors in one launch
// ============================================================================
__global__ void f2h_all_kernel(const float* __restrict__ x,  const float* __restrict__ Wq,
                               const float* __restrict__ Wk, const float* __restrict__ Wo,
                               __half* __restrict__ xh, __half* __restrict__ wq,
                               __half* __restrict__ wk, __half* __restrict__ wo)
{
    const int NX = (M_ * E_) / 4;
    const int NW = (E_ * E_) / 4;
    int i = blockIdx.x * blockDim.x + threadIdx.x;
    const float* in;
    __half* out;
    int off;
    if (i < NX) { in = x; out = xh; off = i; }
    else {
        int j = i - NX;
        int seg = j / NW, r = j - seg * NW;
        in  = (seg == 0) ? Wq : (seg == 1) ? Wk : Wo;
        out = (seg == 0) ? wq : (seg == 1) ? wk : wo;
        off = r;
    }
    float4 v = ((const float4*)in)[off];
    ((__half2*)out)[2*off]     = __floats2half2_rn(v.x, v.y);
    ((__half2*)out)[2*off + 1] = __floats2half2_rn(v.z, v.w);
}

// ============================================================================
// fp16 tensor-core NT GEMM — EXACT R11 config (measured best).
// CTA 128x128, BK=64, 256 thr, warps 2(M)x4(N), warp tile 64x32.
// 3-stage cp.async pipeline, one sync per k-tile. DUAL=1: bx&1 selects W/C.
// ============================================================================
#define GT_BYTES 16384
#define STG_BYTES (2 * GT_BYTES)
#define GEMM_SMEM (3 * STG_BYTES)

template<int BIAS, int DUAL>
__global__ void __launch_bounds__(256, 2)
gemm_h_kernel(const __half* __restrict__ A, const __half* __restrict__ W,
              const float* __restrict__ bias, void* __restrict__ Cout,
              const __half* __restrict__ W2, void* __restrict__ Cout2,
              int M, int N, int K)
{
    extern __shared__ __half smh[];
    const uint32_t uS = (uint32_t)__cvta_generic_to_shared(smh);

    const int tid = threadIdx.x;
    const int wid = tid >> 5, lane = tid & 31;
    const int g = lane >> 2, tig = lane & 3;
    const int wm = wid & 1, wn = wid >> 1;
    const int row0 = blockIdx.y * 128;
    int col0;
    const __half* Wm;
    void* Cm;
    if (DUAL) {
        col0 = ((int)blockIdx.x >> 1) * 128;
        if (blockIdx.x & 1) { Wm = W2; Cm = Cout2; }
        else                { Wm = W;  Cm = Cout;  }
    } else {
        col0 = blockIdx.x * 128;
        Wm = W; Cm = Cout;
    }

    float acc[4][4][4];
    #pragma unroll
    for (int mi = 0; mi < 4; mi++)
        #pragma unroll
        for (int ni = 0; ni < 4; ni++)
            #pragma unroll
            for (int r = 0; r < 4; r++) acc[mi][ni][r] = 0.f;

    auto tload = [&](int kt, int st) {
        const uint32_t base = uS + st * STG_BYTES;
        #pragma unroll
        for (int j = 0; j < 4; j++) {
            const int idx = tid + 256 * j;
            const int r = idx >> 3, c = idx & 7;
            const uint32_t off = (r * 64 + ((c ^ (r & 7)) << 3)) * 2;
            cp16s(base + off,            A  + (size_t)(row0 + r) * K + kt * 64 + c * 8);
            cp16s(base + GT_BYTES + off, Wm + (size_t)(col0 + r) * K + kt * 64 + c * 8);
        }
    };

    tload(0, 0); cp_commit();
    tload(1, 1); cp_commit();

    const int NT = K >> 6;
    int st = 0;
    for (int kt = 0; kt < NT; kt++) {
        if (kt + 1 < NT) cp_wait1(); else cp_wait0();
        __syncthreads();
        if (kt + 2 < NT) {
            int sp = st + 2; if (sp >= 3) sp -= 3;
            tload(kt + 2, sp); cp_commit();
        }

        const uint32_t bA = uS + st * STG_BYTES;
        const uint32_t bB = bA + GT_BYTES;
        #pragma unroll
        for (int ks = 0; ks < 4; ks++) {
            uint32_t bb[4][2];
            #pragma unroll
            for (int p = 0; p < 2; p++) {
                const int rowb = wn * 32 + p * 16 + (lane & 7) + ((lane >= 16) ? 8 : 0);
                const int ch   = 2 * ks + ((lane >> 3) & 1);
                const uint32_t ad = bB + (rowb * 64 + ((ch ^ (rowb & 7)) << 3)) * 2;
                ldsm4(bb[2*p][0], bb[2*p][1], bb[2*p+1][0], bb[2*p+1][1], ad);
            }
            #pragma unroll
            for (int mi = 0; mi < 4; mi++) {
                const int rowa = wm * 64 + mi * 16 + (lane & 7) + (((lane >> 3) & 1) ? 8 : 0);
                const int ch   = 2 * ks + ((lane >> 4) & 1);
                const uint32_t ad = bA + (rowa * 64 + ((ch ^ (rowa & 7)) << 3)) * 2;
                uint32_t a0, a1, a2, a3;
                ldsm4(a0, a1, a2, a3, ad);
                #pragma unroll
                for (int ni = 0; ni < 4; ni++)
                    mma16816(acc[mi][ni], a0, a1, a2, a3, bb[ni][0], bb[ni][1]);
            }
        }
        if (++st == 3) st = 0;
    }

    #pragma unroll
    for (int mi = 0; mi < 4; mi++) {
        const int r = row0 + wm * 64 + mi * 16 + g;
        #pragma unroll
        for (int ni = 0; ni < 4; ni++) {
            const int c = col0 + wn * 32 + ni * 8 + 2 * tig;
            if (BIAS) {
                float* C = (float*)Cm;
                const float b0 = bias[c], b1 = bias[c + 1];
                *(float2*)(C + (size_t)r * N + c)       = make_float2(acc[mi][ni][0] + b0, acc[mi][ni][1] + b1);
                *(float2*)(C + (size_t)(r + 8) * N + c) = make_float2(acc[mi][ni][2] + b0, acc[mi][ni][3] + b1);
            } else {
                __half* C = (__half*)Cm;
                *(__half2*)(C + (size_t)r * N + c)       = __floats2half2_rn(acc[mi][ni][0], acc[mi][ni][1]);
                *(__half2*)(C + (size_t)(r + 8) * N + c) = __floats2half2_rn(acc[mi][ni][2], acc[mi][ni][3]);
            }
        }
    }
}

// ============================================================================
// fp16 tensor-core causal flash attention — EXACT R11 mainloop structure
// (measured best), plus ONE bit-identical change: warps whose 32 q-rows are
// entirely masked in a tile (warps 0/1 on the last diagonal tile) skip the
// whole QK+softmax+PV body. Their p values are fp16-exact zeros (exp2(-144)
// underflows), so lsum/of are unchanged to the bit. mbar arrivals preserved.
// V = Q (faithful to reference bug). 4 warps x 32 q-rows, mbarrier pipeline.
// ============================================================================
#define AT_STG 4
#define AT_TILE 16384
#define ATTN_SMEM (AT_STG * AT_TILE)

__global__ void __launch_bounds__(128, 2)
attn_h_kernel(const __half* __restrict__ Qh, const __half* __restrict__ Kh,
              __half* __restrict__ Oh)
{
    extern __shared__ __half dynsm[];
    __shared__ uint64_t mbars[8];

    const uint32_t uS = (uint32_t)__cvta_generic_to_shared(dynsm);
    const uint32_t uMF = (uint32_t)__cvta_generic_to_shared(&mbars[0]);
    const uint32_t uME = uMF + 32;

    const int qt = 15 - (int)blockIdx.x;
    const int h  = blockIdx.y;
    const int b  = blockIdx.z;
    const int tid = threadIdx.x;
    const int wid = tid >> 5, lane = tid & 31;
    const int g = lane >> 2, tig = lane & 3;
    const int rbase = qt * 128 + wid * 32 + g;
    const int rmaxw = qt * 128 + wid * 32 + 31;   // max q-row this warp owns

    if (tid == 0) {
        #pragma unroll
        for (int s = 0; s < 4; s++) {
            mbar_init(uMF + 8 * s, 32);
            mbar_init(uME + 8 * s, 128);
        }
    }
    __syncthreads();

    size_t gr[2][2];
    #pragma unroll
    for (int mb = 0; mb < 2; mb++) {
        gr[mb][0] = (size_t)(b * S_ + rbase + mb * 16) * E_ + h * 64;
        gr[mb][1] = gr[mb][0] + (size_t)8 * E_;
    }

    uint32_t qa[2][4][4];
    #pragma unroll
    for (int mb = 0; mb < 2; mb++)
        #pragma unroll
        for (int ks = 0; ks < 4; ks++) {
            const int c0 = 16 * ks + 2 * tig;
            qa[mb][ks][0] = *(const uint32_t*)(Qh + gr[mb][0] + c0);
            qa[mb][ks][1] = *(const uint32_t*)(Qh + gr[mb][1] + c0);
            qa[mb][ks][2] = *(const uint32_t*)(Qh + gr[mb][0] + c0 + 8);
            qa[mb][ks][3] = *(const uint32_t*)(Qh + gr[mb][1] + c0 + 8);
        }

    float of[2][8][4];
    #pragma unroll
    for (int mb = 0; mb < 2; mb++)
        #pragma unroll
        for (int nj = 0; nj < 8; nj++)
            #pragma unroll
            for (int r = 0; r < 4; r++) of[mb][nj][r] = 0.f;
    float lsum[2][2] = {{0.f, 0.f}, {0.f, 0.f}};

    const int nkt = 2 * qt + 2;

    auto produce = [&](int kt) {
        const int s = kt & 3;
        const int r = kt >> 2;
        if (r > 0) mbar_wait(uME + 8 * s, (uint32_t)((r - 1) & 1));
        const uint32_t base = uS + s * AT_TILE;
        #pragma unroll
        for (int j = 0; j < 16; j++) {
            const int idx = lane + 32 * j;
            const int rr = idx >> 3, cc = idx & 7;
            const uint32_t off = (rr * 64 + ((cc ^ (rr & 7)) << 3)) * 2;
            const size_t gsrc = (size_t)(b * S_ + kt * 64 + rr) * E_ + h * 64 + cc * 8;
            cp16s(base + off,        Kh + gsrc);
            cp16s(base + 8192 + off, Qh + gsrc);   // V = Q
        }
        cp_async_mbar_arrive_noinc(uMF + 8 * s);
    };

    #pragma unroll
    for (int kp = 0; kp < 3; kp++)
        if (kp < nkt && (kp & 3) == wid) produce(kp);

    for (int kt = 0; kt < nkt; kt++) {
        {
            const int kp = kt + 3;
            if (kp < nkt && (kp & 3) == wid) produce(kp);
        }
        const int s = kt & 3;
        mbar_wait(uMF + 8 * s, (uint32_t)((kt >> 2) & 1));

        // warp-tile fully masked? (keys all > every q-row this warp owns)
        if (kt * 64 > rmaxw) {
            mbar_arrive(uME + 8 * s);
            continue;
        }

        const uint32_t bK = uS + s * AT_TILE;
        const uint32_t bV = bK + 8192;

        float sf[2][8][4];
        #pragma unroll
        for (int mb = 0; mb < 2; mb++)
            #pragma unroll
            for (int ni = 0; ni < 8; ni++)
                #pragma unroll
                for (int r = 0; r < 4; r++) sf[mb][ni][r] = 0.f;

        #pragma unroll
        for (int ks = 0; ks < 4; ks++) {
            uint32_t bb[8][2];
            #pragma unroll
            for (int p = 0; p < 4; p++) {
                const int rowb = p * 16 + (lane & 7) + ((lane >= 16) ? 8 : 0);
                const int ch   = 2 * ks + ((lane >> 3) & 1);
                const uint32_t ad = bK + (rowb * 64 + ((ch ^ (rowb & 7)) << 3)) * 2;
                ldsm4(bb[2*p][0], bb[2*p][1], bb[2*p+1][0], bb[2*p+1][1], ad);
            }
            #pragma unroll
            for (int ni = 0; ni < 8; ni++) {
                mma16816(sf[0][ni], qa[0][ks][0], qa[0][ks][1], qa[0][ks][2], qa[0][ks][3],
                         bb[ni][0], bb[ni][1]);
                mma16816(sf[1][ni], qa[1][ks][0], qa[1][ks][1], qa[1][ks][2], qa[1][ks][3],
                         bb[ni][0], bb[ni][1]);
            }
        }

        const float FS = 0.03125f * 1.44269504f;
        uint32_t ph[2][2][8];
        if (kt >= 2 * qt) {
            const int k0 = kt * 64;
            #pragma unroll
            for (int mb = 0; mb < 2; mb++) {
                const int rq = rbase + mb * 16;
                __half2 ls0 = __floats2half2_rn(0.f, 0.f), ls1 = ls0;
                #pragma unroll
                for (int ni = 0; ni < 8; ni++) {
                    const int kc = k0 + ni * 8 + 2 * tig;
                    float t0 = (kc     <= rq)     ? sf[mb][ni][0] * FS : -100.f;
                    float t1 = (kc + 1 <= rq)     ? sf[mb][ni][1] * FS : -100.f;
                    float t2 = (kc     <= rq + 8) ? sf[mb][ni][2] * FS : -100.f;
                    float t3 = (kc + 1 <= rq + 8) ? sf[mb][ni][3] * FS : -100.f;
                    ph[mb][0][ni] = h2exp2(h2u(__floats2half2_rn(t0, t1)));
                    ph[mb][1][ni] = h2exp2(h2u(__floats2half2_rn(t2, t3)));
                    ls0 = __hadd2(ls0, *(__half2*)&ph[mb][0][ni]);
                    ls1 = __hadd2(ls1, *(__half2*)&ph[mb][1][ni]);
                }
                float2 f0 = __half22float2(ls0);
                float2 f1 = __half22float2(ls1);
                lsum[mb][0] += f0.x + f0.y;
                lsum[mb][1] += f1.x + f1.y;
            }
        } else {
            #pragma unroll
            for (int mb = 0; mb < 2; mb++) {
                __half2 ls0 = __floats2half2_rn(0.f, 0.f), ls1 = ls0;
                #pragma unroll
                for (int ni = 0; ni < 8; ni++) {
                    ph[mb][0][ni] = h2exp2(h2u(__floats2half2_rn(sf[mb][ni][0] * FS, sf[mb][ni][1] * FS)));
                    ph[mb][1][ni] = h2exp2(h2u(__floats2half2_rn(sf[mb][ni][2] * FS, sf[mb][ni][3] * FS)));
                    ls0 = __hadd2(ls0, *(__half2*)&ph[mb][0][ni]);
                    ls1 = __hadd2(ls1, *(__half2*)&ph[mb][1][ni]);
                }
                float2 f0 = __half22float2(ls0);
                float2 f1 = __half22float2(ls1);
                lsum[mb][0] += f0.x + f0.y;
                lsum[mb][1] += f1.x + f1.y;
            }
        }

        #pragma unroll
        for (int ks = 0; ks < 4; ks++) {
            uint32_t bb[8][2];
            #pragma unroll
            for (int p = 0; p < 4; p++) {
                const int rowb = 16 * ks + (lane & 7) + (((lane >> 3) & 1) ? 8 : 0);
                const int ch   = 2 * p + ((lane >= 16) ? 1 : 0);
                const uint32_t ad = bV + (rowb * 64 + ((ch ^ (rowb & 7)) << 3)) * 2;
                ldsm4t(bb[2*p][0], bb[2*p][1], bb[2*p+1][0], bb[2*p+1][1], ad);
            }
            #pragma unroll
            for (int nj = 0; nj < 8; nj++) {
                mma16816(of[0][nj], ph[0][0][2*ks], ph[0][1][2*ks],
                         ph[0][0][2*ks+1], ph[0][1][2*ks+1], bb[nj][0], bb[nj][1]);
                mma16816(of[1][nj], ph[1][0][2*ks], ph[1][1][2*ks],
                         ph[1][0][2*ks+1], ph[1][1][2*ks+1], bb[nj][0], bb[nj][1]);
            }
        }

        mbar_arrive(uME + 8 * s);
    }

    #pragma unroll
    for (int mb = 0; mb < 2; mb++) {
        float l0 = lsum[mb][0], l1 = lsum[mb][1];
        l0 += __shfl_xor_sync(0xffffffffu, l0, 1);
        l0 += __shfl_xor_sync(0xffffffffu, l0, 2);
        l1 += __shfl_xor_sync(0xffffffffu, l1, 1);
        l1 += __shfl_xor_sync(0xffffffffu, l1, 2);
        const float i0 = 1.f / l0, i1 = 1.f / l1;
        #pragma unroll
        for (int nj = 0; nj < 8; nj++) {
            const int c = nj * 8 + 2 * tig;
            *(__half2*)(Oh + gr[mb][0] + c) = __floats2half2_rn(of[mb][nj][0] * i0, of[mb][nj][1] * i0);
            *(__half2*)(Oh + gr[mb][1] + c) = __floats2half2_rn(of[mb][nj][2] * i1, of[mb][nj][3] * i1);
        }
    }
}

// ============================================================================
// launch
// ============================================================================
extern "C" void kernel_launch(void* const* d_in, const int* in_sizes, int n_in,
                              void* d_out, int out_size)
{
    (void)in_sizes; (void)n_in; (void)out_size;
    const float* x  = (const float*)d_in[0];
    const float* Wk = (const float*)d_in[1];
    const float* Wq = (const float*)d_in[2];
    // d_in[3] = Wv — computed-then-discarded in the reference; skipped.
    const float* Wo = (const float*)d_in[4];
    const float* bo = (const float*)d_in[5];
    float* out = (float*)d_out;

    __half *xh, *wq, *wk, *wo, *Qp, *Kp, *Ap;
    cudaGetSymbolAddress((void**)&xh, g_xh);
    cudaGetSymbolAddress((void**)&wq, g_Wq);
    cudaGetSymbolAddress((void**)&wk, g_Wk);
    cudaGetSymbolAddress((void**)&wo, g_Wo);
    cudaGetSymbolAddress((void**)&Qp, g_Qh);
    cudaGetSymbolAddress((void**)&Kp, g_Kh);
    cudaGetSymbolAddress((void**)&Ap, g_Ah);

    cudaFuncSetAttribute(gemm_h_kernel<0,1>, cudaFuncAttributeMaxDynamicSharedMemorySize, GEMM_SMEM);
    cudaFuncSetAttribute(gemm_h_kernel<1,0>, cudaFuncAttributeMaxDynamicSharedMemorySize, GEMM_SMEM);
    cudaFuncSetAttribute(attn_h_kernel,      cudaFuncAttributeMaxDynamicSharedMemorySize, ATTN_SMEM);

    const int NTOT = (M_ * E_ + 3 * E_ * E_) / 4;
    f2h_all_kernel<<<NTOT / 256, 256>>>(x, Wq, Wk, Wo, xh, wq, wk, wo);

    // fused Q+K projections: blockIdx.x&1 selects weight/output
    dim3 qkGrid(2 * E_ / 128, M_ / 128);   // (16, 64)
    gemm_h_kernel<0,1><<<qkGrid, 256, GEMM_SMEM>>>(xh, wq, nullptr, Qp, wk, Kp, M_, E_, E_);

    dim3 aGrid(S_ / 128, H_, B_);          // (16, 16, 4)
    attn_h_kernel<<<aGrid, 128, ATTN_SMEM>>>(Qp, Kp, Ap);

    dim3 oGrid(E_ / 128, M_ / 128);        // (8, 64)
    gemm_h_kernel<1,0><<<oGrid, 256, GEMM_SMEM>>>(Ap, wo, bo, out, nullptr, nullptr, M_, E_, E_);
}

// round 15
// speedup vs baseline: 1.1474x; 1.0157x over previous
#include <cuda_runtime.h>
#include <cuda_fp16.h>
#include <cstdint>
#include <math.h>

#define B_ 4
#define S_ 2048
#define E_ 1024
#define H_ 16
#define D_ 64
#define M_ (B_*S_)   // 8192

// ---- scratch (static device allocations; runtime alloc is forbidden) ----
__device__ __half g_xh[(size_t)M_*E_];
__device__ __half g_Wq[(size_t)E_*E_];
__device__ __half g_Wk[(size_t)E_*E_];
__device__ __half g_Wo[(size_t)E_*E_];
__device__ __half g_Qh[(size_t)M_*E_];   // Q projection (fp16); also serves as V
__device__ __half g_Kh[(size_t)M_*E_];   // K projection (fp16)
__device__ __half g_Ah[(size_t)M_*E_];   // attention output (fp16)

// ============================ helpers (baseline ISA) ============================
__device__ __forceinline__ void cp16s(uint32_t dst, const void* src) {
    asm volatile("cp.async.cg.shared.global [%0], [%1], 16;" :: "r"(dst), "l"(src));
}
__device__ __forceinline__ void cp_commit() { asm volatile("cp.async.commit_group;"); }
__device__ __forceinline__ void cp_wait0()  { asm volatile("cp.async.wait_group 0;"); }
__device__ __forceinline__ void cp_wait1()  { asm volatile("cp.async.wait_group 1;"); }
__device__ __forceinline__ void cp_wait2()  { asm volatile("cp.async.wait_group 2;"); }

__device__ __forceinline__ void mbar_init(uint32_t a, uint32_t n) {
    asm volatile("mbarrier.init.shared.b64 [%0], %1;" :: "r"(a), "r"(n) : "memory");
}
__device__ __forceinline__ void mbar_arrive(uint32_t a) {
    asm volatile("mbarrier.arrive.shared.b64 _, [%0];" :: "r"(a) : "memory");
}
__device__ __forceinline__ void cp_async_mbar_arrive_noinc(uint32_t a) {
    asm volatile("cp.async.mbarrier.arrive.noinc.shared::cta.b64 [%0];" :: "r"(a) : "memory");
}
__device__ __forceinline__ void mbar_wait(uint32_t a, uint32_t parity) {
    asm volatile(
        "{\n\t.reg .pred P;\n\t"
        "WAITLP_%=:\n\t"
        "mbarrier.try_wait.parity.acquire.cta.shared::cta.b64 P, [%0], %1, 0x989680;\n\t"
        "@P bra.uni WAITDN_%=;\n\t"
        "bra.uni WAITLP_%=;\n\t"
        "WAITDN_%=:\n\t}"
        :: "r"(a), "r"(parity) : "memory");
}

__device__ __forceinline__ void ldsm4(uint32_t& r0, uint32_t& r1, uint32_t& r2, uint32_t& r3,
                                      uint32_t addr) {
    asm volatile("ldmatrix.sync.aligned.m8n8.x4.shared.b16 {%0,%1,%2,%3}, [%4];"
                 : "=r"(r0), "=r"(r1), "=r"(r2), "=r"(r3) : "r"(addr));
}
__device__ __forceinline__ void ldsm4t(uint32_t& r0, uint32_t& r1, uint32_t& r2, uint32_t& r3,
                                       uint32_t addr) {
    asm volatile("ldmatrix.sync.aligned.m8n8.x4.trans.shared.b16 {%0,%1,%2,%3}, [%4];"
                 : "=r"(r0), "=r"(r1), "=r"(r2), "=r"(r3) : "r"(addr));
}
__device__ __forceinline__ void mma16816(float* c, uint32_t a0, uint32_t a1, uint32_t a2,
                                         uint32_t a3, uint32_t b0, uint32_t b1) {
    asm volatile(
        "mma.sync.aligned.m16n8k16.row.col.f32.f16.f16.f32 "
        "{%0,%1,%2,%3},{%4,%5,%6,%7},{%8,%9},{%0,%1,%2,%3};"
        : "+f"(c[0]), "+f"(c[1]), "+f"(c[2]), "+f"(c[3])
        : "r"(a0), "r"(a1), "r"(a2), "r"(a3), "r"(b0), "r"(b1));
}
__device__ __forceinline__ uint32_t h2u(__half2 h) { return *(uint32_t*)&h; }
__device__ __forceinline__ uint32_t h2exp2(uint32_t x) {
    uint32_t r;
    asm volatile("ex2.approx.f16x2 %0, %1;" : "=r"(r) : "r"(x));
    return r;
}

// ============================ tcgen05 helpers (sm_103a-only pass) ============================
#if defined(__CUDA_ARCH_FEAT_SM103_ALL)
__device__ __forceinline__ void tc_alloc(uint32_t dst_smem, uint32_t ncols) {
    asm volatile("tcgen05.alloc.cta_group::1.sync.aligned.shared::cta.b32 [%0], %1;"
                 :: "r"(dst_smem), "r"(ncols) : "memory");
}
__device__ __forceinline__ void tc_relinq() {
    asm volatile("tcgen05.relinquish_alloc_permit.cta_group::1.sync.aligned;");
}
__device__ __forceinline__ void tc_dealloc(uint32_t tmem, uint32_t ncols) {
    asm volatile("tcgen05.dealloc.cta_group::1.sync.aligned.b32 %0, %1;" :: "r"(tmem), "r"(ncols));
}
__device__ __forceinline__ void tc_commit(uint32_t mbar) {
    asm volatile("tcgen05.commit.cta_group::1.mbarrier::arrive::one.shared::cluster.b64 [%0];"
                 :: "r"(mbar) : "memory");
}
__device__ __forceinline__ void tc_fence_after()  { asm volatile("tcgen05.fence::after_thread_sync;"  ::: "memory"); }
__device__ __forceinline__ void tc_fence_before() { asm volatile("tcgen05.fence::before_thread_sync;" ::: "memory"); }
__device__ __forceinline__ void fence_pa() { asm volatile("fence.proxy.async.shared::cta;" ::: "memory"); }
__device__ __forceinline__ void ldtm_wait() { asm volatile("tcgen05.wait::ld.sync.aligned;" ::: "memory"); }
__device__ __forceinline__ uint32_t elect1() {
    uint32_t p;
    asm volatile("{\n\t.reg .pred p;\n\telect.sync _|p, 0xFFFFFFFF;\n\tselp.b32 %0, 1, 0, p;\n\t}" : "=r"(p));
    return p;
}
__device__ __forceinline__ void tc_mma_f16_ss(uint32_t d, uint64_t ad, uint64_t bd,
                                              uint32_t idesc, uint32_t en) {
    asm volatile(
        "{\n\t.reg .pred p;\n\tsetp.ne.u32 p, %5, 0;\n\t"
        "tcgen05.mma.cta_group::1.kind::f16 [%0], %1, %2, %3, {%4,%4,%4,%4}, p;\n\t}"
        :: "r"(d), "l"(ad), "l"(bd), "r"(idesc), "r"(0u), "r"(en) : "memory");
}
#define LDTM_X32(r, a) \
    asm volatile( \
        "tcgen05.ld.sync.aligned.32x32b.x32.b32 " \
        "{%0, %1, %2, %3, %4, %5, %6, %7, " \
        " %8, %9, %10, %11, %12, %13, %14, %15, " \
        " %16, %17, %18, %19, %20, %21, %22, %23, " \
        " %24, %25, %26, %27, %28, %29, %30, %31}, [%32];" \
        : "=r"((r)[0]),  "=r"((r)[1]),  "=r"((r)[2]),  "=r"((r)[3]), \
          "=r"((r)[4]),  "=r"((r)[5]),  "=r"((r)[6]),  "=r"((r)[7]), \
          "=r"((r)[8]),  "=r"((r)[9]),  "=r"((r)[10]), "=r"((r)[11]), \
          "=r"((r)[12]), "=r"((r)[13]), "=r"((r)[14]), "=r"((r)[15]), \
          "=r"((r)[16]), "=r"((r)[17]), "=r"((r)[18]), "=r"((r)[19]), \
          "=r"((r)[20]), "=r"((r)[21]), "=r"((r)[22]), "=r"((r)[23]), \
          "=r"((r)[24]), "=r"((r)[25]), "=r"((r)[26]), "=r"((r)[27]), \
          "=r"((r)[28]), "=r"((r)[29]), "=r"((r)[30]), "=r"((r)[31]) \
        : "r"(a))
__device__ __forceinline__ uint64_t make_desc_sw128(uint32_t base) {
    // layout=SW128(2), version=1 (Blackwell), SBO=64 (1024B), LBO=1 (16B)
    const uint64_t BASE = ((uint64_t)2 << 61) | ((uint64_t)1 << 46) |
                          ((uint64_t)64 << 32) | ((uint64_t)1 << 16);
    return BASE | ((uint64_t)(base >> 4) & 0x3FFF);
}
// idesc kind::f16: D=F32(1<<4), A=F16(0), B=F16(0), N=128 ((128/8)<<17), M=128 ((128/16)<<24)
#define IDESC_F16 0x8200010u
#endif

// ============================================================================
// fp32 -> fp16 convert, ALL tensors in one launch
// ============================================================================
__global__ void f2h_all_kernel(const float* __restrict__ x,  const float* __restrict__ Wq,
                               const float* __restrict__ Wk, const float* __restrict__ Wo,
                               __half* __restrict__ xh, __half* __restrict__ wq,
                               __half* __restrict__ wk, __half* __restrict__ wo)
{
    const int NX = (M_ * E_) / 4;
    const int NW = (E_ * E_) / 4;
    int i = blockIdx.x * blockDim.x + threadIdx.x;
    const float* in;
    __half* out;
    int off;
    if (i < NX) { in = x; out = xh; off = i; }
    else {
        int j = i - NX;
        int seg = j / NW, r = j - seg * NW;
        in  = (seg == 0) ? Wq : (seg == 1) ? Wk : Wo;
        out = (seg == 0) ? wq : (seg == 1) ? wk : wo;
        off = r;
    }
    float4 v = ((const float4*)in)[off];
    ((__half2*)out)[2*off]     = __floats2half2_rn(v.x, v.y);
    ((__half2*)out)[2*off + 1] = __floats2half2_rn(v.z, v.w);
}

// ============================================================================
// fp16 NT GEMM. Same cp.async 3-stage pipeline + SW128-pattern smem tiles.
// On the sm_103a compile pass: tcgen05 SS MMA (TMEM accumulator, LDTM epilog).
// On the baseline compute_103 pass: proven mma.sync path (R11 config).
// DUAL=1: blockIdx.x&1 selects (W,C) vs (W2,C2).
// ============================================================================
#define GT_BYTES 16384
#define STG_BYTES (2 * GT_BYTES)
#define GEMM_SMEM (1024 + 3 * STG_BYTES + 64)

template<int BIAS, int DUAL>
__global__ void __launch_bounds__(256, 2) __cluster_dims__(1, 1, 1)
gemm_h_kernel(const __half* __restrict__ A, const __half* __restrict__ W,
              const float* __restrict__ bias, void* __restrict__ Cout,
              const __half* __restrict__ W2, void* __restrict__ Cout2,
              int M, int N, int K)
{
    extern __shared__ __half smh[];
    char* smal = (char*)((((uintptr_t)smh) + 1023) & ~(uintptr_t)1023);  // 1024-align (SW128 abs pattern)
    const uint32_t uS = (uint32_t)__cvta_generic_to_shared(smal);

    const int tid = threadIdx.x;
    const int wid = tid >> 5, lane = tid & 31;
    const int row0 = blockIdx.y * 128;
    int col0;
    const __half* Wm;
    void* Cm;
    if (DUAL) {
        col0 = ((int)blockIdx.x >> 1) * 128;
        if (blockIdx.x & 1) { Wm = W2; Cm = Cout2; }
        else                { Wm = W;  Cm = Cout;  }
    } else {
        col0 = blockIdx.x * 128;
        Wm = W; Cm = Cout;
    }

    auto tload = [&](int kt, int st) {
        const uint32_t base = uS + st * STG_BYTES;
        #pragma unroll
        for (int j = 0; j < 4; j++) {
            const int idx = tid + 256 * j;
            const int r = idx >> 3, c = idx & 7;
            const uint32_t off = (r * 64 + ((c ^ (r & 7)) << 3)) * 2;   // == SW128 swizzle
            cp16s(base + off,            A  + (size_t)(row0 + r) * K + kt * 64 + c * 8);
            cp16s(base + GT_BYTES + off, Wm + (size_t)(col0 + r) * K + kt * 64 + c * 8);
        }
    };
    const int NT = K >> 6;

#if defined(__CUDA_ARCH_FEAT_SM103_ALL)
    // ======================= tcgen05 path (sm_103a) =======================
    const uint32_t uTM  = uS + 3 * STG_BYTES;        // tmem ptr slot
    const uint32_t uMB  = uTM + 8;                   // stage mbars [0..2]
    const uint32_t uMBF = uMB + 24;                  // final mbar

    if (wid == 0) tc_alloc(uTM, 128);
    if (tid == 0) {
        mbar_init(uMB + 0, 1);
        mbar_init(uMB + 8, 1);
        mbar_init(uMB + 16, 1);
        mbar_init(uMBF, 1);
    }
    __syncthreads();
    uint32_t tmem;
    asm volatile("ld.shared.b32 %0, [%1];" : "=r"(tmem) : "r"(uTM));

    tload(0, 0); cp_commit();
    tload(1, 1); cp_commit();

    for (int kt = 0; kt < NT; kt++) {
        const int st = kt % 3;
        const int tp = kt + 2;
        if (tp < NT) {
            if (kt >= 1) {
                // stage tp%3 last used by tile tp-3: wait its MMA completion
                mbar_wait(uMB + 8 * (tp % 3), (uint32_t)((tp / 3 - 1) & 1));
            }
            tload(tp, tp % 3); cp_commit();
            cp_wait2();                     // tile kt's data resident
        } else if (kt == NT - 2) {
            cp_wait1();
        } else {
            cp_wait0();
        }
        fence_pa();
        __syncthreads();

        if (wid == 0 && elect1()) {
            const uint64_t ad = make_desc_sw128(uS + st * STG_BYTES);
            const uint64_t bd = make_desc_sw128(uS + st * STG_BYTES + GT_BYTES);
            #pragma unroll
            for (int ks = 0; ks < 4; ks++)   // 4 x (K=16) per 64-half tile; +2 units = +32B
                tc_mma_f16_ss(tmem, ad + 2 * ks, bd + 2 * ks, IDESC_F16,
                              (kt > 0 || ks > 0) ? 1u : 0u);
            tc_commit(uMB + 8 * st);
        }
    }

    if (wid == 0 && elect1()) tc_commit(uMBF);   // covers all prior MMAs
    mbar_wait(uMBF, 0);
    tc_fence_after();

    // epilogue: warps 0-3 read their 32-lane TMEM subpartition, 4 x 32 cols
    if (wid < 4) {
        const int r = row0 + wid * 32 + lane;
        #pragma unroll 1
        for (int c0 = 0; c0 < 128; c0 += 32) {
            uint32_t dr[32];
            LDTM_X32(dr, tmem + c0);
            ldtm_wait();
            if (BIAS) {
                float* C = (float*)Cm;
                float* dst = C + (size_t)r * N + col0 + c0;
                #pragma unroll
                for (int j = 0; j < 32; j += 4) {
                    float4 v;
                    v.x = __uint_as_float(dr[j + 0]) + bias[col0 + c0 + j + 0];
                    v.y = __uint_as_float(dr[j + 1]) + bias[col0 + c0 + j + 1];
                    v.z = __uint_as_float(dr[j + 2]) + bias[col0 + c0 + j + 2];
                    v.w = __uint_as_float(dr[j + 3]) + bias[col0 + c0 + j + 3];
                    *(float4*)(dst + j) = v;
                }
            } else {
                __half* C = (__half*)Cm;
                __half2* dst = (__half2*)(C + (size_t)r * N + col0 + c0);
                #pragma unroll
                for (int j = 0; j < 32; j += 2)
                    dst[j >> 1] = __floats2half2_rn(__uint_as_float(dr[j]),
                                                    __uint_as_float(dr[j + 1]));
            }
        }
        tc_fence_before();
    }
    __syncthreads();
    if (wid == 0) { tc_relinq(); tc_dealloc(tmem, 128); }

#else
    // ======================= mma.sync fallback (baseline ISA) =======================
    const int g = lane >> 2, tig = lane & 3;
    const int wm = wid & 1, wn = wid >> 1;

    float acc[4][4][4];
    #pragma unroll
    for (int mi = 0; mi < 4; mi++)
        #pragma unroll
        for (int ni = 0; ni < 4; ni++)
            #pragma unroll
            for (int r = 0; r < 4; r++) acc[mi][ni][r] = 0.f;

    tload(0, 0); cp_commit();
    tload(1, 1); cp_commit();

    int st = 0;
    for (int kt = 0; kt < NT; kt++) {
        if (kt + 1 < NT) cp_wait1(); else cp_wait0();
        __syncthreads();
        if (kt + 2 < NT) {
            int sp = st + 2; if (sp >= 3) sp -= 3;
            tload(kt + 2, sp); cp_commit();
        }

        const uint32_t bA = uS + st * STG_BYTES;
        const uint32_t bB = bA + GT_BYTES;
        #pragma unroll
        for (int ks = 0; ks < 4; ks++) {
            uint32_t bb[4][2];
            #pragma unroll
            for (int p = 0; p < 2; p++) {
                const int rowb = wn * 32 + p * 16 + (lane & 7) + ((lane >= 16) ? 8 : 0);
                const int ch   = 2 * ks + ((lane >> 3) & 1);
                const uint32_t ad = bB + (rowb * 64 + ((ch ^ (rowb & 7)) << 3)) * 2;
                ldsm4(bb[2*p][0], bb[2*p][1], bb[2*p+1][0], bb[2*p+1][1], ad);
            }
            #pragma unroll
            for (int mi = 0; mi < 4; mi++) {
                const int rowa = wm * 64 + mi * 16 + (lane & 7) + (((lane >> 3) & 1) ? 8 : 0);
                const int ch   = 2 * ks + ((lane >> 4) & 1);
                const uint32_t ad = bA + (rowa * 64 + ((ch ^ (rowa & 7)) << 3)) * 2;
                uint32_t a0, a1, a2, a3;
                ldsm4(a0, a1, a2, a3, ad);
                #pragma unroll
                for (int ni = 0; ni < 4; ni++)
                    mma16816(acc[mi][ni], a0, a1, a2, a3, bb[ni][0], bb[ni][1]);
            }
        }
        if (++st == 3) st = 0;
    }

    #pragma unroll
    for (int mi = 0; mi < 4; mi++) {
        const int r = row0 + wm * 64 + mi * 16 + g;
        #pragma unroll
        for (int ni = 0; ni < 4; ni++) {
            const int c = col0 + wn * 32 + ni * 8 + 2 * tig;
            if (BIAS) {
                float* C = (float*)Cm;
                const float b0 = bias[c], b1 = bias[c + 1];
                *(float2*)(C + (size_t)r * N + c)       = make_float2(acc[mi][ni][0] + b0, acc[mi][ni][1] + b1);
                *(float2*)(C + (size_t)(r + 8) * N + c) = make_float2(acc[mi][ni][2] + b0, acc[mi][ni][3] + b1);
            } else {
                __half* C = (__half*)Cm;
                *(__half2*)(C + (size_t)r * N + c)       = __floats2half2_rn(acc[mi][ni][0], acc[mi][ni][1]);
                *(__half2*)(C + (size_t)(r + 8) * N + c) = __floats2half2_rn(acc[mi][ni][2], acc[mi][ni][3]);
            }
        }
    }
#endif
}

// ============================================================================
// fp16 tensor-core causal flash attention — R14 (best known), unchanged.
// V = Q (faithful to reference bug). 4 warps x 32 q-rows, mbarrier pipeline,
// fully-masked warp-tiles skipped (bit-identical: their p underflow to 0).
// ============================================================================
#define AT_STG 4
#define AT_TILE 16384
#define ATTN_SMEM (AT_STG * AT_TILE)

__global__ void __launch_bounds__(128, 2)
attn_h_kernel(const __half* __restrict__ Qh, const __half* __restrict__ Kh,
              __half* __restrict__ Oh)
{
    extern __shared__ __half dynsm[];
    __shared__ uint64_t mbars[8];

    const uint32_t uS = (uint32_t)__cvta_generic_to_shared(dynsm);
    const uint32_t uMF = (uint32_t)__cvta_generic_to_shared(&mbars[0]);
    const uint32_t uME = uMF + 32;

    const int qt = 15 - (int)blockIdx.x;
    const int h  = blockIdx.y;
    const int b  = blockIdx.z;
    const int tid = threadIdx.x;
    const int wid = tid >> 5, lane = tid & 31;
    const int g = lane >> 2, tig = lane & 3;
    const int rbase = qt * 128 + wid * 32 + g;
    const int rmaxw = qt * 128 + wid * 32 + 31;

    if (tid == 0) {
        #pragma unroll
        for (int s = 0; s < 4; s++) {
            mbar_init(uMF + 8 * s, 32);
            mbar_init(uME + 8 * s, 128);
        }
    }
    __syncthreads();

    size_t gr[2][2];
    #pragma unroll
    for (int mb = 0; mb < 2; mb++) {
        gr[mb][0] = (size_t)(b * S_ + rbase + mb * 16) * E_ + h * 64;
        gr[mb][1] = gr[mb][0] + (size_t)8 * E_;
    }

    uint32_t qa[2][4][4];
    #pragma unroll
    for (int mb = 0; mb < 2; mb++)
        #pragma unroll
        for (int ks = 0; ks < 4; ks++) {
            const int c0 = 16 * ks + 2 * tig;
            qa[mb][ks][0] = *(const uint32_t*)(Qh + gr[mb][0] + c0);
            qa[mb][ks][1] = *(const uint32_t*)(Qh + gr[mb][1] + c0);
            qa[mb][ks][2] = *(const uint32_t*)(Qh + gr[mb][0] + c0 + 8);
            qa[mb][ks][3] = *(const uint32_t*)(Qh + gr[mb][1] + c0 + 8);
        }

    float of[2][8][4];
    #pragma unroll
    for (int mb = 0; mb < 2; mb++)
        #pragma unroll
        for (int nj = 0; nj < 8; nj++)
            #pragma unroll
            for (int r = 0; r < 4; r++) of[mb][nj][r] = 0.f;
    float lsum[2][2] = {{0.f, 0.f}, {0.f, 0.f}};

    const int nkt = 2 * qt + 2;

    auto produce = [&](int kt) {
        const int s = kt & 3;
        const int r = kt >> 2;
        if (r > 0) mbar_wait(uME + 8 * s, (uint32_t)((r - 1) & 1));
        const uint32_t base = uS + s * AT_TILE;
        #pragma unroll
        for (int j = 0; j < 16; j++) {
            const int idx = lane + 32 * j;
            const int rr = idx >> 3, cc = idx & 7;
            const uint32_t off = (rr * 64 + ((cc ^ (rr & 7)) << 3)) * 2;
            const size_t gsrc = (size_t)(b * S_ + kt * 64 + rr) * E_ + h * 64 + cc * 8;
            cp16s(base + off,        Kh + gsrc);
            cp16s(base + 8192 + off, Qh + gsrc);   // V = Q
        }
        cp_async_mbar_arrive_noinc(uMF + 8 * s);
    };

    #pragma unroll
    for (int kp = 0; kp < 3; kp++)
        if (kp < nkt && (kp & 3) == wid) produce(kp);

    for (int kt = 0; kt < nkt; kt++) {
        {
            const int kp = kt + 3;
            if (kp < nkt && (kp & 3) == wid) produce(kp);
        }
        const int s = kt & 3;
        mbar_wait(uMF + 8 * s, (uint32_t)((kt >> 2) & 1));

        if (kt * 64 > rmaxw) {            // warp-tile fully masked
            mbar_arrive(uME + 8 * s);
            continue;
        }

        const uint32_t bK = uS + s * AT_TILE;
        const uint32_t bV = bK + 8192;

        float sf[2][8][4];
        #pragma unroll
        for (int mb = 0; mb < 2; mb++)
            #pragma unroll
            for (int ni = 0; ni < 8; ni++)
                #pragma unroll
                for (int r = 0; r < 4; r++) sf[mb][ni][r] = 0.f;

        #pragma unroll
        for (int ks = 0; ks < 4; ks++) {
            uint32_t bb[8][2];
            #pragma unroll
            for (int p = 0; p < 4; p++) {
                const int rowb = p * 16 + (lane & 7) + ((lane >= 16) ? 8 : 0);
                const int ch   = 2 * ks + ((lane >> 3) & 1);
                const uint32_t ad = bK + (rowb * 64 + ((ch ^ (rowb & 7)) << 3)) * 2;
                ldsm4(bb[2*p][0], bb[2*p][1], bb[2*p+1][0], bb[2*p+1][1], ad);
            }
            #pragma unroll
            for (int ni = 0; ni < 8; ni++) {
                mma16816(sf[0][ni], qa[0][ks][0], qa[0][ks][1], qa[0][ks][2], qa[0][ks][3],
                         bb[ni][0], bb[ni][1]);
                mma16816(sf[1][ni], qa[1][ks][0], qa[1][ks][1], qa[1][ks][2], qa[1][ks][3],
                         bb[ni][0], bb[ni][1]);
            }
        }

        const float FS = 0.03125f * 1.44269504f;
        uint32_t ph[2][2][8];
        if (kt >= 2 * qt) {
            const int k0 = kt * 64;
            #pragma unroll
            for (int mb = 0; mb < 2; mb++) {
                const int rq = rbase + mb * 16;
                __half2 ls0 = __floats2half2_rn(0.f, 0.f), ls1 = ls0;
                #pragma unroll
                for (int ni = 0; ni < 8; ni++) {
                    const int kc = k0 + ni * 8 + 2 * tig;
                    float t0 = (kc     <= rq)     ? sf[mb][ni][0] * FS : -100.f;
                    float t1 = (kc + 1 <= rq)     ? sf[mb][ni][1] * FS : -100.f;
                    float t2 = (kc     <= rq + 8) ? sf[mb][ni][2] * FS : -100.f;
                    float t3 = (kc + 1 <= rq + 8) ? sf[mb][ni][3] * FS : -100.f;
                    ph[mb][0][ni] = h2exp2(h2u(__floats2half2_rn(t0, t1)));
                    ph[mb][1][ni] = h2exp2(h2u(__floats2half2_rn(t2, t3)));
                    ls0 = __hadd2(ls0, *(__half2*)&ph[mb][0][ni]);
                    ls1 = __hadd2(ls1, *(__half2*)&ph[mb][1][ni]);
                }
                float2 f0 = __half22float2(ls0);
                float2 f1 = __half22float2(ls1);
                lsum[mb][0] += f0.x + f0.y;
                lsum[mb][1] += f1.x + f1.y;
            }
        } else {
            #pragma unroll
            for (int mb = 0; mb < 2; mb++) {
                __half2 ls0 = __floats2half2_rn(0.f, 0.f), ls1 = ls0;
                #pragma unroll
                for (int ni = 0; ni < 8; ni++) {
                    ph[mb][0][ni] = h2exp2(h2u(__floats2half2_rn(sf[mb][ni][0] * FS, sf[mb][ni][1] * FS)));
                    ph[mb][1][ni] = h2exp2(h2u(__floats2half2_rn(sf[mb][ni][2] * FS, sf[mb][ni][3] * FS)));
                    ls0 = __hadd2(ls0, *(__half2*)&ph[mb][0][ni]);
                    ls1 = __hadd2(ls1, *(__half2*)&ph[mb][1][ni]);
                }
                float2 f0 = __half22float2(ls0);
                float2 f1 = __half22float2(ls1);
                lsum[mb][0] += f0.x + f0.y;
                lsum[mb][1] += f1.x + f1.y;
            }
        }

        #pragma unroll
        for (int ks = 0; ks < 4; ks++) {
            uint32_t bb[8][2];
            #pragma unroll
            for (int p = 0; p < 4; p++) {
                const int rowb = 16 * ks + (lane & 7) + (((lane >> 3) & 1) ? 8 : 0);
                const int ch   = 2 * p + ((lane >= 16) ? 1 : 0);
                const uint32_t ad = bV + (rowb * 64 + ((ch ^ (rowb & 7)) << 3)) * 2;
                ldsm4t(bb[2*p][0], bb[2*p][1], bb[2*p+1][0], bb[2*p+1][1], ad);
            }
            #pragma unroll
            for (int nj = 0; nj < 8; nj++) {
                mma16816(of[0][nj], ph[0][0][2*ks], ph[0][1][2*ks],
                         ph[0][0][2*ks+1], ph[0][1][2*ks+1], bb[nj][0], bb[nj][1]);
                mma16816(of[1][nj], ph[1][0][2*ks], ph[1][1][2*ks],
                         ph[1][0][2*ks+1], ph[1][1][2*ks+1], bb[nj][0], bb[nj][1]);
            }
        }

        mbar_arrive(uME + 8 * s);
    }

    #pragma unroll
    for (int mb = 0; mb < 2; mb++) {
        float l0 = lsum[mb][0], l1 = lsum[mb][1];
        l0 += __shfl_xor_sync(0xffffffffu, l0, 1);
        l0 += __shfl_xor_sync(0xffffffffu, l0, 2);
        l1 += __shfl_xor_sync(0xffffffffu, l1, 1);
        l1 += __shfl_xor_sync(0xffffffffu, l1, 2);
        const float i0 = 1.f / l0, i1 = 1.f / l1;
        #pragma unroll
        for (int nj = 0; nj < 8; nj++) {
            const int c = nj * 8 + 2 * tig;
            *(__half2*)(Oh + gr[mb][0] + c) = __floats2half2_rn(of[mb][nj][0] * i0, of[mb][nj][1] * i0);
            *(__half2*)(Oh + gr[mb][1] + c) = __floats2half2_rn(of[mb][nj][2] * i1, of[mb][nj][3] * i1);
        }
    }
}

// ============================================================================
// launch
// ============================================================================
extern "C" void kernel_launch(void* const* d_in, const int* in_sizes, int n_in,
                              void* d_out, int out_size)
{
    (void)in_sizes; (void)n_in; (void)out_size;
    const float* x  = (const float*)d_in[0];
    const float* Wk = (const float*)d_in[1];
    const float* Wq = (const float*)d_in[2];
    // d_in[3] = Wv — computed-then-discarded in the reference; skipped.
    const float* Wo = (const float*)d_in[4];
    const float* bo = (const float*)d_in[5];
    float* out = (float*)d_out;

    __half *xh, *wq, *wk, *wo, *Qp, *Kp, *Ap;
    cudaGetSymbolAddress((void**)&xh, g_xh);
    cudaGetSymbolAddress((void**)&wq, g_Wq);
    cudaGetSymbolAddress((void**)&wk, g_Wk);
    cudaGetSymbolAddress((void**)&wo, g_Wo);
    cudaGetSymbolAddress((void**)&Qp, g_Qh);
    cudaGetSymbolAddress((void**)&Kp, g_Kh);
    cudaGetSymbolAddress((void**)&Ap, g_Ah);

    cudaFuncSetAttribute(gemm_h_kernel<0,1>, cudaFuncAttributeMaxDynamicSharedMemorySize, GEMM_SMEM);
    cudaFuncSetAttribute(gemm_h_kernel<1,0>, cudaFuncAttributeMaxDynamicSharedMemorySize, GEMM_SMEM);
    cudaFuncSetAttribute(attn_h_kernel,      cudaFuncAttributeMaxDynamicSharedMemorySize, ATTN_SMEM);

    const int NTOT = (M_ * E_ + 3 * E_ * E_) / 4;
    f2h_all_kernel<<<NTOT / 256, 256>>>(x, Wq, Wk, Wo, xh, wq, wk, wo);

    // fused Q+K projections: blockIdx.x&1 selects weight/output
    dim3 qkGrid(2 * E_ / 128, M_ / 128);   // (16, 64)
    gemm_h_kernel<0,1><<<qkGrid, 256, GEMM_SMEM>>>(xh, wq, nullptr, Qp, wk, Kp, M_, E_, E_);

    dim3 aGrid(S_ / 128, H_, B_);          // (16, 16, 4)
    attn_h_kernel<<<aGrid, 128, ATTN_SMEM>>>(Qp, Kp, Ap);

    dim3 oGrid(E_ / 128, M_ / 128);        // (8, 64)
    gemm_h_kernel<1,0><<<oGrid, 256, GEMM_SMEM>>>(Ap, wo, bo, out, nullptr, nullptr, M_, E_, E_);
}

// round 16
// speedup vs baseline: 1.1607x; 1.0116x over previous
#include <cuda_runtime.h>
#include <cuda_fp16.h>
#include <cstdint>
#include <math.h>

#define B_ 4
#define S_ 2048
#define E_ 1024
#define H_ 16
#define D_ 64
#define M_ (B_*S_)   // 8192

// ---- scratch (static device allocations; runtime alloc is forbidden) ----
__device__ __half g_xh[(size_t)M_*E_];
__device__ __half g_Wq[(size_t)E_*E_];
__device__ __half g_Wk[(size_t)E_*E_];
__device__ __half g_Wo[(size_t)E_*E_];
__device__ __half g_Qh[(size_t)M_*E_];   // Q projection (fp16); also serves as V
__device__ __half g_Kh[(size_t)M_*E_];   // K projection (fp16)
__device__ __half g_Ah[(size_t)M_*E_];   // attention output (fp16)

// ============================ helpers (baseline ISA) ============================
__device__ __forceinline__ void cp16s(uint32_t dst, const void* src) {
    asm volatile("cp.async.cg.shared.global [%0], [%1], 16;" :: "r"(dst), "l"(src));
}
__device__ __forceinline__ void cp_commit() { asm volatile("cp.async.commit_group;"); }
__device__ __forceinline__ void cp_wait0()  { asm volatile("cp.async.wait_group 0;"); }
__device__ __forceinline__ void cp_wait1()  { asm volatile("cp.async.wait_group 1;"); }

__device__ __forceinline__ void mbar_init(uint32_t a, uint32_t n) {
    asm volatile("mbarrier.init.shared.b64 [%0], %1;" :: "r"(a), "r"(n) : "memory");
}
__device__ __forceinline__ void mbar_arrive(uint32_t a) {
    asm volatile("mbarrier.arrive.shared.b64 _, [%0];" :: "r"(a) : "memory");
}
__device__ __forceinline__ void cp_async_mbar_arrive_noinc(uint32_t a) {
    asm volatile("cp.async.mbarrier.arrive.noinc.shared::cta.b64 [%0];" :: "r"(a) : "memory");
}
__device__ __forceinline__ void mbar_wait(uint32_t a, uint32_t parity) {
    asm volatile(
        "{\n\t.reg .pred P;\n\t"
        "WAITLP_%=:\n\t"
        "mbarrier.try_wait.parity.acquire.cta.shared::cta.b64 P, [%0], %1, 0x989680;\n\t"
        "@P bra.uni WAITDN_%=;\n\t"
        "bra.uni WAITLP_%=;\n\t"
        "WAITDN_%=:\n\t}"
        :: "r"(a), "r"(parity) : "memory");
}

__device__ __forceinline__ void ldsm4(uint32_t& r0, uint32_t& r1, uint32_t& r2, uint32_t& r3,
                                      uint32_t addr) {
    asm volatile("ldmatrix.sync.aligned.m8n8.x4.shared.b16 {%0,%1,%2,%3}, [%4];"
                 : "=r"(r0), "=r"(r1), "=r"(r2), "=r"(r3) : "r"(addr));
}
__device__ __forceinline__ void ldsm4t(uint32_t& r0, uint32_t& r1, uint32_t& r2, uint32_t& r3,
                                       uint32_t addr) {
    asm volatile("ldmatrix.sync.aligned.m8n8.x4.trans.shared.b16 {%0,%1,%2,%3}, [%4];"
                 : "=r"(r0), "=r"(r1), "=r"(r2), "=r"(r3) : "r"(addr));
}
__device__ __forceinline__ void mma16816(float* c, uint32_t a0, uint32_t a1, uint32_t a2,
                                         uint32_t a3, uint32_t b0, uint32_t b1) {
    asm volatile(
        "mma.sync.aligned.m16n8k16.row.col.f32.f16.f16.f32 "
        "{%0,%1,%2,%3},{%4,%5,%6,%7},{%8,%9},{%0,%1,%2,%3};"
        : "+f"(c[0]), "+f"(c[1]), "+f"(c[2]), "+f"(c[3])
        : "r"(a0), "r"(a1), "r"(a2), "r"(a3), "r"(b0), "r"(b1));
}
__device__ __forceinline__ uint32_t h2u(__half2 h) { return *(uint32_t*)&h; }
__device__ __forceinline__ uint32_t h2exp2(uint32_t x) {
    uint32_t r;
    asm volatile("ex2.approx.f16x2 %0, %1;" : "=r"(r) : "r"(x));
    return r;
}

// ============================ tcgen05 helpers (sm_103a-only pass) ============================
#if defined(__CUDA_ARCH_FEAT_SM103_ALL)
__device__ __forceinline__ void tc_alloc(uint32_t dst_smem, uint32_t ncols) {
    asm volatile("tcgen05.alloc.cta_group::1.sync.aligned.shared::cta.b32 [%0], %1;"
                 :: "r"(dst_smem), "r"(ncols) : "memory");
}
__device__ __forceinline__ void tc_relinq() {
    asm volatile("tcgen05.relinquish_alloc_permit.cta_group::1.sync.aligned;");
}
__device__ __forceinline__ void tc_dealloc(uint32_t tmem, uint32_t ncols) {
    asm volatile("tcgen05.dealloc.cta_group::1.sync.aligned.b32 %0, %1;" :: "r"(tmem), "r"(ncols));
}
__device__ __forceinline__ void tc_commit(uint32_t mbar) {
    asm volatile("tcgen05.commit.cta_group::1.mbarrier::arrive::one.shared::cluster.b64 [%0];"
                 :: "r"(mbar) : "memory");
}
__device__ __forceinline__ void tc_fence_after()  { asm volatile("tcgen05.fence::after_thread_sync;"  ::: "memory"); }
__device__ __forceinline__ void tc_fence_before() { asm volatile("tcgen05.fence::before_thread_sync;" ::: "memory"); }
__device__ __forceinline__ void fence_pa() { asm volatile("fence.proxy.async.shared::cta;" ::: "memory"); }
__device__ __forceinline__ void ldtm_wait() { asm volatile("tcgen05.wait::ld.sync.aligned;" ::: "memory"); }
__device__ __forceinline__ uint32_t elect1() {
    uint32_t p;
    asm volatile("{\n\t.reg .pred p;\n\telect.sync _|p, 0xFFFFFFFF;\n\tselp.b32 %0, 1, 0, p;\n\t}" : "=r"(p));
    return p;
}
__device__ __forceinline__ void tc_mma_f16_ss(uint32_t d, uint64_t ad, uint64_t bd,
                                              uint32_t idesc, uint32_t en) {
    asm volatile(
        "{\n\t.reg .pred p;\n\tsetp.ne.u32 p, %5, 0;\n\t"
        "tcgen05.mma.cta_group::1.kind::f16 [%0], %1, %2, %3, {%4,%4,%4,%4}, p;\n\t}"
        :: "r"(d), "l"(ad), "l"(bd), "r"(idesc), "r"(0u), "r"(en) : "memory");
}
#define LDTM_X32(r, a) \
    asm volatile( \
        "tcgen05.ld.sync.aligned.32x32b.x32.b32 " \
        "{%0, %1, %2, %3, %4, %5, %6, %7, " \
        " %8, %9, %10, %11, %12, %13, %14, %15, " \
        " %16, %17, %18, %19, %20, %21, %22, %23, " \
        " %24, %25, %26, %27, %28, %29, %30, %31}, [%32];" \
        : "=r"((r)[0]),  "=r"((r)[1]),  "=r"((r)[2]),  "=r"((r)[3]), \
          "=r"((r)[4]),  "=r"((r)[5]),  "=r"((r)[6]),  "=r"((r)[7]), \
          "=r"((r)[8]),  "=r"((r)[9]),  "=r"((r)[10]), "=r"((r)[11]), \
          "=r"((r)[12]), "=r"((r)[13]), "=r"((r)[14]), "=r"((r)[15]), \
          "=r"((r)[16]), "=r"((r)[17]), "=r"((r)[18]), "=r"((r)[19]), \
          "=r"((r)[20]), "=r"((r)[21]), "=r"((r)[22]), "=r"((r)[23]), \
          "=r"((r)[24]), "=r"((r)[25]), "=r"((r)[26]), "=r"((r)[27]), \
          "=r"((r)[28]), "=r"((r)[29]), "=r"((r)[30]), "=r"((r)[31]) \
        : "r"(a))
__device__ __forceinline__ uint64_t make_desc_sw128(uint32_t base) {
    const uint64_t BASE = ((uint64_t)2 << 61) | ((uint64_t)1 << 46) |
                          ((uint64_t)64 << 32) | ((uint64_t)1 << 16);
    return BASE | ((uint64_t)(base >> 4) & 0x3FFF);
}
#define IDESC_F16 0x8200010u
#endif

// ============================================================================
// fp32 -> fp16 convert, ALL tensors in one launch
// ============================================================================
__global__ void f2h_all_kernel(const float* __restrict__ x,  const float* __restrict__ Wq,
                               const float* __restrict__ Wk, const float* __restrict__ Wo,
                               __half* __restrict__ xh, __half* __restrict__ wq,
                               __half* __restrict__ wk, __half* __restrict__ wo)
{
    const int NX = (M_ * E_) / 4;
    const int NW = (E_ * E_) / 4;
    int i = blockIdx.x * blockDim.x + threadIdx.x;
    const float* in;
    __half* out;
    int off;
    if (i < NX) { in = x; out = xh; off = i; }
    else {
        int j = i - NX;
        int seg = j / NW, r = j - seg * NW;
        in  = (seg == 0) ? Wq : (seg == 1) ? Wk : Wo;
        out = (seg == 0) ? wq : (seg == 1) ? wk : wo;
        off = r;
    }
    float4 v = ((const float4*)in)[off];
    ((__half2*)out)[2*off]     = __floats2half2_rn(v.x, v.y);
    ((__half2*)out)[2*off + 1] = __floats2half2_rn(v.z, v.w);
}

// ============================================================================
// fp16 NT GEMM, SW128 smem tiles, 3 stages.
// sm_103a pass: tcgen05 SS MMA with FULLY ASYNC mbarrier pipeline —
//   full[s] (count 256): per-thread cp.async.mbarrier.arrive.noinc on tile load
//   done[s] (count 1):   tcgen05.commit; producers wait it before stage reuse
//   NO __syncthreads / cp.async.wait_group in the mainloop.
// Baseline pass: proven mma.sync path (R11 config), unchanged.
// ============================================================================
#define GT_BYTES 16384
#define STG_BYTES (2 * GT_BYTES)
#define GEMM_SMEM (1024 + 3 * STG_BYTES + 128)

template<int BIAS, int DUAL>
__global__ void __launch_bounds__(256, 2) __cluster_dims__(1, 1, 1)
gemm_h_kernel(const __half* __restrict__ A, const __half* __restrict__ W,
              const float* __restrict__ bias, void* __restrict__ Cout,
              const __half* __restrict__ W2, void* __restrict__ Cout2,
              int M, int N, int K)
{
    extern __shared__ __half smh[];
    char* smal = (char*)((((uintptr_t)smh) + 1023) & ~(uintptr_t)1023);
    const uint32_t uS = (uint32_t)__cvta_generic_to_shared(smal);

    const int tid = threadIdx.x;
    const int wid = tid >> 5, lane = tid & 31;
    const int row0 = blockIdx.y * 128;
    int col0;
    const __half* Wm;
    void* Cm;
    if (DUAL) {
        col0 = ((int)blockIdx.x >> 1) * 128;
        if (blockIdx.x & 1) { Wm = W2; Cm = Cout2; }
        else                { Wm = W;  Cm = Cout;  }
    } else {
        col0 = blockIdx.x * 128;
        Wm = W; Cm = Cout;
    }

    auto tload = [&](int kt, int st) {
        const uint32_t base = uS + st * STG_BYTES;
        #pragma unroll
        for (int j = 0; j < 4; j++) {
            const int idx = tid + 256 * j;
            const int r = idx >> 3, c = idx & 7;
            const uint32_t off = (r * 64 + ((c ^ (r & 7)) << 3)) * 2;   // SW128 swizzle
            cp16s(base + off,            A  + (size_t)(row0 + r) * K + kt * 64 + c * 8);
            cp16s(base + GT_BYTES + off, Wm + (size_t)(col0 + r) * K + kt * 64 + c * 8);
        }
    };
    const int NT = K >> 6;

#if defined(__CUDA_ARCH_FEAT_SM103_ALL)
    // ======================= tcgen05 path (sm_103a) =======================
    const uint32_t uCTRL = uS + 3 * STG_BYTES;
    const uint32_t uTM   = uCTRL;          // tmem ptr slot (8B)
    const uint32_t uFull = uCTRL + 8;      // full[0..2]
    const uint32_t uDone = uCTRL + 32;     // done[0..2]
    const uint32_t uMBF  = uCTRL + 56;     // final

    if (wid == 0) tc_alloc(uTM, 128);
    if (tid == 0) {
        #pragma unroll
        for (int s = 0; s < 3; s++) {
            mbar_init(uFull + 8 * s, 256);   // all threads' load completion
            mbar_init(uDone + 8 * s, 1);     // MMA commit
        }
        mbar_init(uMBF, 1);
    }
    __syncthreads();
    uint32_t tmem;
    asm volatile("ld.shared.b32 %0, [%1];" : "=r"(tmem) : "r"(uTM));

    // prologue: tiles 0,1 (stages 0,1) — per-thread arrive tracks completion
    tload(0, 0); cp_async_mbar_arrive_noinc(uFull + 0);
    tload(1, 1); cp_async_mbar_arrive_noinc(uFull + 8);

    for (int kt = 0; kt < NT; kt++) {
        // producer: tile kt+2 into stage (kt+2)%3 after its MMA round drains
        const int tp = kt + 2;
        if (tp < NT) {
            const int sp = tp % 3;
            const int rp = tp / 3;
            if (rp > 0) mbar_wait(uDone + 8 * sp, (uint32_t)((rp - 1) & 1));
            tload(tp, sp);
            cp_async_mbar_arrive_noinc(uFull + 8 * sp);
        }
        // consumer: elected thread of warp 0 issues the MMA chain
        if (wid == 0 && elect1()) {
            const int s = kt % 3;
            mbar_wait(uFull + 8 * s, (uint32_t)((kt / 3) & 1));
            const uint64_t ad = make_desc_sw128(uS + s * STG_BYTES);
            const uint64_t bd = make_desc_sw128(uS + s * STG_BYTES + GT_BYTES);
            #pragma unroll
            for (int ks = 0; ks < 4; ks++)
                tc_mma_f16_ss(tmem, ad + 2 * ks, bd + 2 * ks, IDESC_F16,
                              (kt > 0 || ks > 0) ? 1u : 0u);
            tc_commit(uDone + 8 * s);
        }
    }

    if (wid == 0 && elect1()) tc_commit(uMBF);   // covers all prior MMAs
    mbar_wait(uMBF, 0);
    tc_fence_after();

    // epilogue: warps 0-3 read their 32-lane TMEM subpartition, 4 x 32 cols
    if (wid < 4) {
        const int r = row0 + wid * 32 + lane;
        #pragma unroll 1
        for (int c0 = 0; c0 < 128; c0 += 32) {
            uint32_t dr[32];
            LDTM_X32(dr, tmem + c0);
            ldtm_wait();
            if (BIAS) {
                float* C = (float*)Cm;
                float* dst = C + (size_t)r * N + col0 + c0;
                #pragma unroll
                for (int j = 0; j < 32; j += 4) {
                    float4 v;
                    v.x = __uint_as_float(dr[j + 0]) + bias[col0 + c0 + j + 0];
                    v.y = __uint_as_float(dr[j + 1]) + bias[col0 + c0 + j + 1];
                    v.z = __uint_as_float(dr[j + 2]) + bias[col0 + c0 + j + 2];
                    v.w = __uint_as_float(dr[j + 3]) + bias[col0 + c0 + j + 3];
                    *(float4*)(dst + j) = v;
                }
            } else {
                __half* C = (__half*)Cm;
                __half2* dst = (__half2*)(C + (size_t)r * N + col0 + c0);
                #pragma unroll
                for (int j = 0; j < 32; j += 2)
                    dst[j >> 1] = __floats2half2_rn(__uint_as_float(dr[j]),
                                                    __uint_as_float(dr[j + 1]));
            }
        }
        tc_fence_before();
    }
    __syncthreads();
    if (wid == 0) { tc_relinq(); tc_dealloc(tmem, 128); }

#else
    // ======================= mma.sync fallback (baseline ISA) =======================
    const int g = lane >> 2, tig = lane & 3;
    const int wm = wid & 1, wn = wid >> 1;

    float acc[4][4][4];
    #pragma unroll
    for (int mi = 0; mi < 4; mi++)
        #pragma unroll
        for (int ni = 0; ni < 4; ni++)
            #pragma unroll
            for (int r = 0; r < 4; r++) acc[mi][ni][r] = 0.f;

    tload(0, 0); cp_commit();
    tload(1, 1); cp_commit();

    int st = 0;
    for (int kt = 0; kt < NT; kt++) {
        if (kt + 1 < NT) cp_wait1(); else cp_wait0();
        __syncthreads();
        if (kt + 2 < NT) {
            int sp = st + 2; if (sp >= 3) sp -= 3;
            tload(kt + 2, sp); cp_commit();
        }

        const uint32_t bA = uS + st * STG_BYTES;
        const uint32_t bB = bA + GT_BYTES;
        #pragma unroll
        for (int ks = 0; ks < 4; ks++) {
            uint32_t bb[4][2];
            #pragma unroll
            for (int p = 0; p < 2; p++) {
                const int rowb = wn * 32 + p * 16 + (lane & 7) + ((lane >= 16) ? 8 : 0);
                const int ch   = 2 * ks + ((lane >> 3) & 1);
                const uint32_t ad = bB + (rowb * 64 + ((ch ^ (rowb & 7)) << 3)) * 2;
                ldsm4(bb[2*p][0], bb[2*p][1], bb[2*p+1][0], bb[2*p+1][1], ad);
            }
            #pragma unroll
            for (int mi = 0; mi < 4; mi++) {
                const int rowa = wm * 64 + mi * 16 + (lane & 7) + (((lane >> 3) & 1) ? 8 : 0);
                const int ch   = 2 * ks + ((lane >> 4) & 1);
                const uint32_t ad = bA + (rowa * 64 + ((ch ^ (rowa & 7)) << 3)) * 2;
                uint32_t a0, a1, a2, a3;
                ldsm4(a0, a1, a2, a3, ad);
                #pragma unroll
                for (int ni = 0; ni < 4; ni++)
                    mma16816(acc[mi][ni], a0, a1, a2, a3, bb[ni][0], bb[ni][1]);
            }
        }
        if (++st == 3) st = 0;
    }

    #pragma unroll
    for (int mi = 0; mi < 4; mi++) {
        const int r = row0 + wm * 64 + mi * 16 + g;
        #pragma unroll
        for (int ni = 0; ni < 4; ni++) {
            const int c = col0 + wn * 32 + ni * 8 + 2 * tig;
            if (BIAS) {
                float* C = (float*)Cm;
                const float b0 = bias[c], b1 = bias[c + 1];
                *(float2*)(C + (size_t)r * N + c)       = make_float2(acc[mi][ni][0] + b0, acc[mi][ni][1] + b1);
                *(float2*)(C + (size_t)(r + 8) * N + c) = make_float2(acc[mi][ni][2] + b0, acc[mi][ni][3] + b1);
            } else {
                __half* C = (__half*)Cm;
                *(__half2*)(C + (size_t)r * N + c)       = __floats2half2_rn(acc[mi][ni][0], acc[mi][ni][1]);
                *(__half2*)(C + (size_t)(r + 8) * N + c) = __floats2half2_rn(acc[mi][ni][2], acc[mi][ni][3]);
            }
        }
    }
#endif
}

// ============================================================================
// fp16 tensor-core causal flash attention — R14 (best known), unchanged.
// V = Q (faithful to reference bug). 4 warps x 32 q-rows, mbarrier pipeline,
// fully-masked warp-tiles skipped (bit-identical: their p underflow to 0).
// ============================================================================
#define AT_STG 4
#define AT_TILE 16384
#define ATTN_SMEM (AT_STG * AT_TILE)

__global__ void __launch_bounds__(128, 2)
attn_h_kernel(const __half* __restrict__ Qh, const __half* __restrict__ Kh,
              __half* __restrict__ Oh)
{
    extern __shared__ __half dynsm[];
    __shared__ uint64_t mbars[8];

    const uint32_t uS = (uint32_t)__cvta_generic_to_shared(dynsm);
    const uint32_t uMF = (uint32_t)__cvta_generic_to_shared(&mbars[0]);
    const uint32_t uME = uMF + 32;

    const int qt = 15 - (int)blockIdx.x;
    const int h  = blockIdx.y;
    const int b  = blockIdx.z;
    const int tid = threadIdx.x;
    const int wid = tid >> 5, lane = tid & 31;
    const int g = lane >> 2, tig = lane & 3;
    const int rbase = qt * 128 + wid * 32 + g;
    const int rmaxw = qt * 128 + wid * 32 + 31;

    if (tid == 0) {
        #pragma unroll
        for (int s = 0; s < 4; s++) {
            mbar_init(uMF + 8 * s, 32);
            mbar_init(uME + 8 * s, 128);
        }
    }
    __syncthreads();

    size_t gr[2][2];
    #pragma unroll
    for (int mb = 0; mb < 2; mb++) {
        gr[mb][0] = (size_t)(b * S_ + rbase + mb * 16) * E_ + h * 64;
        gr[mb][1] = gr[mb][0] + (size_t)8 * E_;
    }

    uint32_t qa[2][4][4];
    #pragma unroll
    for (int mb = 0; mb < 2; mb++)
        #pragma unroll
        for (int ks = 0; ks < 4; ks++) {
            const int c0 = 16 * ks + 2 * tig;
            qa[mb][ks][0] = *(const uint32_t*)(Qh + gr[mb][0] + c0);
            qa[mb][ks][1] = *(const uint32_t*)(Qh + gr[mb][1] + c0);
            qa[mb][ks][2] = *(const uint32_t*)(Qh + gr[mb][0] + c0 + 8);
            qa[mb][ks][3] = *(const uint32_t*)(Qh + gr[mb][1] + c0 + 8);
        }

    float of[2][8][4];
    #pragma unroll
    for (int mb = 0; mb < 2; mb++)
        #pragma unroll
        for (int nj = 0; nj < 8; nj++)
            #pragma unroll
            for (int r = 0; r < 4; r++) of[mb][nj][r] = 0.f;
    float lsum[2][2] = {{0.f, 0.f}, {0.f, 0.f}};

    const int nkt = 2 * qt + 2;

    auto produce = [&](int kt) {
        const int s = kt & 3;
        const int r = kt >> 2;
        if (r > 0) mbar_wait(uME + 8 * s, (uint32_t)((r - 1) & 1));
        const uint32_t base = uS + s * AT_TILE;
        #pragma unroll
        for (int j = 0; j < 16; j++) {
            const int idx = lane + 32 * j;
            const int rr = idx >> 3, cc = idx & 7;
            const uint32_t off = (rr * 64 + ((cc ^ (rr & 7)) << 3)) * 2;
            const size_t gsrc = (size_t)(b * S_ + kt * 64 + rr) * E_ + h * 64 + cc * 8;
            cp16s(base + off,        Kh + gsrc);
            cp16s(base + 8192 + off, Qh + gsrc);   // V = Q
        }
        cp_async_mbar_arrive_noinc(uMF + 8 * s);
    };

    #pragma unroll
    for (int kp = 0; kp < 3; kp++)
        if (kp < nkt && (kp & 3) == wid) produce(kp);

    for (int kt = 0; kt < nkt; kt++) {
        {
            const int kp = kt + 3;
            if (kp < nkt && (kp & 3) == wid) produce(kp);
        }
        const int s = kt & 3;
        mbar_wait(uMF + 8 * s, (uint32_t)((kt >> 2) & 1));

        if (kt * 64 > rmaxw) {            // warp-tile fully masked
            mbar_arrive(uME + 8 * s);
            continue;
        }

        const uint32_t bK = uS + s * AT_TILE;
        const uint32_t bV = bK + 8192;

        float sf[2][8][4];
        #pragma unroll
        for (int mb = 0; mb < 2; mb++)
            #pragma unroll
            for (int ni = 0; ni < 8; ni++)
                #pragma unroll
                for (int r = 0; r < 4; r++) sf[mb][ni][r] = 0.f;

        #pragma unroll
        for (int ks = 0; ks < 4; ks++) {
            uint32_t bb[8][2];
            #pragma unroll
            for (int p = 0; p < 4; p++) {
                const int rowb = p * 16 + (lane & 7) + ((lane >= 16) ? 8 : 0);
                const int ch   = 2 * ks + ((lane >> 3) & 1);
                const uint32_t ad = bK + (rowb * 64 + ((ch ^ (rowb & 7)) << 3)) * 2;
                ldsm4(bb[2*p][0], bb[2*p][1], bb[2*p+1][0], bb[2*p+1][1], ad);
            }
            #pragma unroll
            for (int ni = 0; ni < 8; ni++) {
                mma16816(sf[0][ni], qa[0][ks][0], qa[0][ks][1], qa[0][ks][2], qa[0][ks][3],
                         bb[ni][0], bb[ni][1]);
                mma16816(sf[1][ni], qa[1][ks][0], qa[1][ks][1], qa[1][ks][2], qa[1][ks][3],
                         bb[ni][0], bb[ni][1]);
            }
        }

        const float FS = 0.03125f * 1.44269504f;
        uint32_t ph[2][2][8];
        if (kt >= 2 * qt) {
            const int k0 = kt * 64;
            #pragma unroll
            for (int mb = 0; mb < 2; mb++) {
                const int rq = rbase + mb * 16;
                __half2 ls0 = __floats2half2_rn(0.f, 0.f), ls1 = ls0;
                #pragma unroll
                for (int ni = 0; ni < 8; ni++) {
                    const int kc = k0 + ni * 8 + 2 * tig;
                    float t0 = (kc     <= rq)     ? sf[mb][ni][0] * FS : -100.f;
                    float t1 = (kc + 1 <= rq)     ? sf[mb][ni][1] * FS : -100.f;
                    float t2 = (kc     <= rq + 8) ? sf[mb][ni][2] * FS : -100.f;
                    float t3 = (kc + 1 <= rq + 8) ? sf[mb][ni][3] * FS : -100.f;
                    ph[mb][0][ni] = h2exp2(h2u(__floats2half2_rn(t0, t1)));
                    ph[mb][1][ni] = h2exp2(h2u(__floats2half2_rn(t2, t3)));
                    ls0 = __hadd2(ls0, *(__half2*)&ph[mb][0][ni]);
                    ls1 = __hadd2(ls1, *(__half2*)&ph[mb][1][ni]);
                }
                float2 f0 = __half22float2(ls0);
                float2 f1 = __half22float2(ls1);
                lsum[mb][0] += f0.x + f0.y;
                lsum[mb][1] += f1.x + f1.y;
            }
        } else {
            #pragma unroll
            for (int mb = 0; mb < 2; mb++) {
                __half2 ls0 = __floats2half2_rn(0.f, 0.f), ls1 = ls0;
                #pragma unroll
                for (int ni = 0; ni < 8; ni++) {
                    ph[mb][0][ni] = h2exp2(h2u(__floats2half2_rn(sf[mb][ni][0] * FS, sf[mb][ni][1] * FS)));
                    ph[mb][1][ni] = h2exp2(h2u(__floats2half2_rn(sf[mb][ni][2] * FS, sf[mb][ni][3] * FS)));
                    ls0 = __hadd2(ls0, *(__half2*)&ph[mb][0][ni]);
                    ls1 = __hadd2(ls1, *(__half2*)&ph[mb][1][ni]);
                }
                float2 f0 = __half22float2(ls0);
                float2 f1 = __half22float2(ls1);
                lsum[mb][0] += f0.x + f0.y;
                lsum[mb][1] += f1.x + f1.y;
            }
        }

        #pragma unroll
        for (int ks = 0; ks < 4; ks++) {
            uint32_t bb[8][2];
            #pragma unroll
            for (int p = 0; p < 4; p++) {
                const int rowb = 16 * ks + (lane & 7) + (((lane >> 3) & 1) ? 8 : 0);
                const int ch   = 2 * p + ((lane >= 16) ? 1 : 0);
                const uint32_t ad = bV + (rowb * 64 + ((ch ^ (rowb & 7)) << 3)) * 2;
                ldsm4t(bb[2*p][0], bb[2*p][1], bb[2*p+1][0], bb[2*p+1][1], ad);
            }
            #pragma unroll
            for (int nj = 0; nj < 8; nj++) {
                mma16816(of[0][nj], ph[0][0][2*ks], ph[0][1][2*ks],
                         ph[0][0][2*ks+1], ph[0][1][2*ks+1], bb[nj][0], bb[nj][1]);
                mma16816(of[1][nj], ph[1][0][2*ks], ph[1][1][2*ks],
                         ph[1][0][2*ks+1], ph[1][1][2*ks+1], bb[nj][0], bb[nj][1]);
            }
        }

        mbar_arrive(uME + 8 * s);
    }

    #pragma unroll
    for (int mb = 0; mb < 2; mb++) {
        float l0 = lsum[mb][0], l1 = lsum[mb][1];
        l0 += __shfl_xor_sync(0xffffffffu, l0, 1);
        l0 += __shfl_xor_sync(0xffffffffu, l0, 2);
        l1 += __shfl_xor_sync(0xffffffffu, l1, 1);
        l1 += __shfl_xor_sync(0xffffffffu, l1, 2);
        const float i0 = 1.f / l0, i1 = 1.f / l1;
        #pragma unroll
        for (int nj = 0; nj < 8; nj++) {
            const int c = nj * 8 + 2 * tig;
            *(__half2*)(Oh + gr[mb][0] + c) = __floats2half2_rn(of[mb][nj][0] * i0, of[mb][nj][1] * i0);
            *(__half2*)(Oh + gr[mb][1] + c) = __floats2half2_rn(of[mb][nj][2] * i1, of[mb][nj][3] * i1);
        }
    }
}

// ============================================================================
// launch
// ============================================================================
extern "C" void kernel_launch(void* const* d_in, const int* in_sizes, int n_in,
                              void* d_out, int out_size)
{
    (void)in_sizes; (void)n_in; (void)out_size;
    const float* x  = (const float*)d_in[0];
    const float* Wk = (const float*)d_in[1];
    const float* Wq = (const float*)d_in[2];
    // d_in[3] = Wv — computed-then-discarded in the reference; skipped.
    const float* Wo = (const float*)d_in[4];
    const float* bo = (const float*)d_in[5];
    float* out = (float*)d_out;

    __half *xh, *wq, *wk, *wo, *Qp, *Kp, *Ap;
    cudaGetSymbolAddress((void**)&xh, g_xh);
    cudaGetSymbolAddress((void**)&wq, g_Wq);
    cudaGetSymbolAddress((void**)&wk, g_Wk);
    cudaGetSymbolAddress((void**)&wo, g_Wo);
    cudaGetSymbolAddress((void**)&Qp, g_Qh);
    cudaGetSymbolAddress((void**)&Kp, g_Kh);
    cudaGetSymbolAddress((void**)&Ap, g_Ah);

    cudaFuncSetAttribute(gemm_h_kernel<0,1>, cudaFuncAttributeMaxDynamicSharedMemorySize, GEMM_SMEM);
    cudaFuncSetAttribute(gemm_h_kernel<1,0>, cudaFuncAttributeMaxDynamicSharedMemorySize, GEMM_SMEM);
    cudaFuncSetAttribute(attn_h_kernel,      cudaFuncAttributeMaxDynamicSharedMemorySize, ATTN_SMEM);

    const int NTOT = (M_ * E_ + 3 * E_ * E_) / 4;
    f2h_all_kernel<<<NTOT / 256, 256>>>(x, Wq, Wk, Wo, xh, wq, wk, wo);

    // fused Q+K projections: blockIdx.x&1 selects weight/output
    dim3 qkGrid(2 * E_ / 128, M_ / 128);   // (16, 64)
    gemm_h_kernel<0,1><<<qkGrid, 256, GEMM_SMEM>>>(xh, wq, nullptr, Qp, wk, Kp, M_, E_, E_);

    dim3 aGrid(S_ / 128, H_, B_);          // (16, 16, 4)
    attn_h_kernel<<<aGrid, 128, ATTN_SMEM>>>(Qp, Kp, Ap);

    dim3 oGrid(E_ / 128, M_ / 128);        // (8, 64)
    gemm_h_kernel<1,0><<<oGrid, 256, GEMM_SMEM>>>(Ap, wo, bo, out, nullptr, nullptr, M_, E_, E_);
}